// round 1
// baseline (speedup 1.0000x reference)
#include <cuda_runtime.h>
#include <math.h>

#define HW      128
#define GRIDN   (HW*HW)
#define NPTS    16

#define D_MAXF  6.4f
#define GRESF   0.1f
#define KSTIFF  5000.0f
#define KDAMP   894.4271909999159f   /* sqrt(4*40*5000) rounded to f32 */
#define KFRIC   0.5f
#define MGRAV   392.40000000000003f  /* MASS*G */
#define MASSF   40.0f
#define DTF     0.01f
#define EPSF    1e-6f

__device__ __forceinline__ float clampidx(float q) {
    float v = (q + D_MAXF) / GRESF;
    return fminf(fmaxf(v, 0.0f), 126.0f);
}

__device__ __forceinline__ float bilin(const float* __restrict__ g, float xi, float yi) {
    float x0f = floorf(xi), y0f = floorf(yi);
    int   x0  = (int)x0f,   y0  = (int)y0f;
    float wx  = xi - x0f,   wy  = yi - y0f;
    const float* r = g + (x0 * HW + y0);
    float z00 = r[0], z01 = r[1], z10 = r[HW], z11 = r[HW + 1];
    return z00 * (1.0f - wx) * (1.0f - wy)
         + z10 * wx          * (1.0f - wy)
         + z01 * (1.0f - wx) * wy
         + z11 * wx          * wy;
}

__device__ __forceinline__ float rk4s(float x, float v, float dt) {
    float k1 = dt * v;
    float k2 = dt * (v + k1 * 0.5f);   /* /2 is exact -> *0.5f identical */
    float k3 = dt * (v + k2 * 0.5f);
    float k4 = dt * (v + k3);
    return x + (k1 + 2.0f * k2 + 2.0f * k3 + k4) / 6.0f;
}

__device__ __forceinline__ float rsum16(float v) {
    v += __shfl_xor_sync(0xffffffffu, v, 1);
    v += __shfl_xor_sync(0xffffffffu, v, 2);
    v += __shfl_xor_sync(0xffffffffu, v, 4);
    v += __shfl_xor_sync(0xffffffffu, v, 8);
    return v;
}

__global__ void __launch_bounds__(128, 1)
physics_kernel(const float* __restrict__ z_grid,
               const float* __restrict__ controls,
               const float* __restrict__ rpts,
               const float* __restrict__ Iinv,
               float* __restrict__ out,
               int T)
{
    extern __shared__ float smem[];
    float* sg = smem;            // HW*HW terrain
    float* sc = smem + GRIDN;    // 2*T controls

    const int b   = blockIdx.x;
    const int tid = threadIdx.x;

    // Stage terrain + controls into shared memory (all 128 threads).
    {
        const float4* src = reinterpret_cast<const float4*>(z_grid + (size_t)b * GRIDN);
        float4*       dst = reinterpret_cast<float4*>(sg);
        #pragma unroll 4
        for (int i = tid; i < GRIDN / 4; i += 128) dst[i] = src[i];
        const float* cs = controls + (size_t)b * T * 2;
        for (int i = tid; i < T * 2; i += 128) sc[i] = cs[i];
    }
    __syncthreads();
    if (tid >= 32) return;       // warps 1..3 done; warp 0 runs the sim

    const int  lane = tid;
    const int  p    = lane & 15;
    const bool act  = lane < 16;

    // robot point (lanes 16..31 mirror 0..15 with valid data; stores masked)
    float rpx = rpts[3 * p + 0], rpy = rpts[3 * p + 1], rpz = rpts[3 * p + 2];

    // cog_y = mean of point y (exact for +-0.25) -> left/right masks
    float my = rsum16(rpy) * (1.0f / 16.0f);
    const bool isL = rpy > my;
    const bool isR = rpy < my;

    const float I00 = Iinv[0], I01 = Iinv[1], I02 = Iinv[2];
    const float I10 = Iinv[3], I11 = Iinv[4], I12 = Iinv[5];
    const float I20 = Iinv[6], I21 = Iinv[7], I22 = Iinv[8];

    // state (replicated on all lanes)
    float Xx = 0.f, Xy = 0.f, Xz = 1.f;
    float Vx = 0.f, Vy = 0.f, Vz = 0.f;
    float Wx = 0.f, Wy = 0.f, Wz = 0.f;
    float R00 = 1.f, R01 = 0.f, R02 = 0.f;
    float R10 = 0.f, R11 = 1.f, R12 = 0.f;
    float R20 = 0.f, R21 = 0.f, R22 = 1.f;
    // per-point state
    float px = rpx, py = rpy, pz = 1.0f + rpz;
    float pvx = 0.f, pvy = 0.f, pvz = 0.f;

    float* outb = out + (size_t)b * T * 162;

    for (int t = 0; t < T; ++t) {
        float ul = sc[2 * t], ur = sc[2 * t + 1];

        // --- terrain sampling (5 bilinear interps, shared y/x index reuse) ---
        float xic = clampidx(px),         yic = clampidx(py);
        float xip = clampidx(px + GRESF), xim = clampidx(px - GRESF);
        float yip = clampidx(py + GRESF), yim = clampidx(py - GRESF);
        float z   = bilin(sg, xic, yic);
        float zxp = bilin(sg, xip, yic);
        float zxm = bilin(sg, xim, yic);
        float zyp = bilin(sg, xic, yip);
        float zym = bilin(sg, xic, yim);

        float dh = pz - z;
        bool  on = (px >= -D_MAXF) && (px <= D_MAXF) &&
                   (py >= -D_MAXF) && (py <= D_MAXF);
        float contact = (dh <= 0.0f && on) ? 1.0f : 0.0f;

        // --- surface normal ---
        float dzdx = (zxp - zxm) / 0.2f;
        float dzdy = (zyp - zym) / 0.2f;
        float nx = -dzdx, ny = -dzdy, nz = 1.0f;
        float nn = sqrtf(nx * nx + ny * ny + nz * nz) + EPSF;
        nx /= nn; ny /= nn; nz /= nn;

        // --- spring/damper normal force ---
        float xdn = pvx * nx + pvy * ny + pvz * nz;
        float fm  = -(KSTIFF * dh + KDAMP * xdn);
        float Fsx = fm * nx * contact;
        float Fsy = fm * ny * contact;
        float Fsz = fm * nz * contact;

        // --- thrust direction = first column of R, normalized ---
        float tx = R00, ty = R10, tz = R20;
        float tn = sqrtf(tx * tx + ty * ty + tz * tz) + EPSF;
        tx /= tn; ty /= tn; tz /= tn;

        // --- friction (left/right select before tanh: identical values) ---
        float Nn = sqrtf(Fsx * Fsx + Fsy * Fsy + Fsz * Fsz);
        float kN = KFRIC * Nn;
        float us = isL ? ul : ur;
        bool  lr = isL || isR;
        float Ffx = lr ? kN * tanhf(us * tx - pvx) : 0.0f;
        float Ffy = lr ? kN * tanhf(us * ty - pvy) : 0.0f;
        float Ffz = lr ? kN * tanhf(us * tz - pvz) : 0.0f;

        // --- torque & force sums over the 16 points ---
        float rx = px - Xx, ry = py - Xy, rz = pz - Xz;
        float Ftx = Fsx + Ffx, Fty = Fsy + Ffy, Ftz = Fsz + Ffz;
        float tqx = ry * Ftz - rz * Fty;
        float tqy = rz * Ftx - rx * Ftz;
        float tqz = rx * Fty - ry * Ftx;

        float Tqx  = rsum16(tqx), Tqy  = rsum16(tqy), Tqz  = rsum16(tqz);
        float SFsx = rsum16(Fsx), SFsy = rsum16(Fsy), SFsz = rsum16(Fsz);
        float SFfx = rsum16(Ffx), SFfy = rsum16(Ffy), SFfz = rsum16(Ffz);

        // omega_dot = I_inv @ torque  (torque @ I_inv.T)
        float odx = Tqx * I00 + Tqy * I01 + Tqz * I02;
        float ody = Tqx * I10 + Tqy * I11 + Tqz * I12;
        float odz = Tqx * I20 + Tqy * I21 + Tqz * I22;

        // F_cog and accel
        float Fcx = 0.0f   + SFsx * (1.0f / 16.0f) + SFfx * (1.0f / 16.0f);
        float Fcy = 0.0f   + SFsy * (1.0f / 16.0f) + SFfy * (1.0f / 16.0f);
        float Fcz = -MGRAV + SFsz * (1.0f / 16.0f) + SFfz * (1.0f / 16.0f);
        float ax = Fcx / MASSF, ay = Fcy / MASSF, az = Fcz / MASSF;

        // new point velocity from OLD body velocity & OLD omega
        float npvx = Vx + (Wy * rz - Wz * ry);
        float npvy = Vy + (Wz * rx - Wx * rz);
        float npvz = Vz + (Wx * ry - Wy * rx);

        // --- integrate (matching reference order: xd first, x uses new xd) ---
        float nVx = rk4s(Vx, ax, DTF), nVy = rk4s(Vy, ay, DTF), nVz = rk4s(Vz, az, DTF);
        float nXx = rk4s(Xx, nVx, DTF), nXy = rk4s(Xy, nVy, DTF), nXz = rk4s(Xz, nVz, DTF);
        float npx = rk4s(px, npvx, DTF), npy = rk4s(py, npvy, DTF), npz = rk4s(pz, npvz, DTF);
        float nWx = rk4s(Wx, odx, DTF), nWy = rk4s(Wy, ody, DTF), nWz = rk4s(Wz, odz, DTF);

        // --- rotation update (Rodrigues with omega_new) ---
        float th = sqrtf(nWx * nWx + nWy * nWy + nWz * nWz);
        float dd = th + EPSF;
        float wx = nWx / dd, wy = nWy / dd, wz = nWz / dd;
        float s  = sinf(th * DTF);
        float c  = 1.0f - cosf(th * DTF);

        float K00 = 0.f,  K01 = -wz, K02 = wy;
        float K10 = wz,   K11 = 0.f, K12 = -wx;
        float K20 = -wy,  K21 = wx,  K22 = 0.f;

        float Q00 = K00*K00 + K01*K10 + K02*K20;
        float Q01 = K00*K01 + K01*K11 + K02*K21;
        float Q02 = K00*K02 + K01*K12 + K02*K22;
        float Q10 = K10*K00 + K11*K10 + K12*K20;
        float Q11 = K10*K01 + K11*K11 + K12*K21;
        float Q12 = K10*K02 + K11*K12 + K12*K22;
        float Q20 = K20*K00 + K21*K10 + K22*K20;
        float Q21 = K20*K01 + K21*K11 + K22*K21;
        float Q22 = K20*K02 + K21*K12 + K22*K22;

        float A00 = 1.0f + K00 * s + Q00 * c;
        float A01 =        K01 * s + Q01 * c;
        float A02 =        K02 * s + Q02 * c;
        float A10 =        K10 * s + Q10 * c;
        float A11 = 1.0f + K11 * s + Q11 * c;
        float A12 =        K12 * s + Q12 * c;
        float A20 =        K20 * s + Q20 * c;
        float A21 =        K21 * s + Q21 * c;
        float A22 = 1.0f + K22 * s + Q22 * c;

        float nR00 = R00*A00 + R01*A10 + R02*A20;
        float nR01 = R00*A01 + R01*A11 + R02*A21;
        float nR02 = R00*A02 + R01*A12 + R02*A22;
        float nR10 = R10*A00 + R11*A10 + R12*A20;
        float nR11 = R10*A01 + R11*A11 + R12*A21;
        float nR12 = R10*A02 + R11*A12 + R12*A22;
        float nR20 = R20*A00 + R21*A10 + R22*A20;
        float nR21 = R20*A01 + R21*A11 + R22*A21;
        float nR22 = R20*A02 + R21*A12 + R22*A22;

        // --- outputs ---
        float* o = outb + (size_t)t * 162;
        if (lane == 0) {
            o[0] = nXx;  o[1] = nXy;  o[2] = nXz;
            o[3] = nVx;  o[4] = nVy;  o[5] = nVz;
            o[6] = nWx;  o[7] = nWy;  o[8] = nWz;
            o[9]  = nR00; o[10] = nR01; o[11] = nR02;
            o[12] = nR10; o[13] = nR11; o[14] = nR12;
            o[15] = nR20; o[16] = nR21; o[17] = nR22;
        }
        if (act) {
            o[18  + 3 * p] = npx; o[19  + 3 * p] = npy; o[20  + 3 * p] = npz;
            o[66  + 3 * p] = Fsx; o[67  + 3 * p] = Fsy; o[68  + 3 * p] = Fsz;
            o[114 + 3 * p] = Ffx; o[115 + 3 * p] = Ffy; o[116 + 3 * p] = Ffz;
        }

        // --- commit state ---
        Xx = nXx; Xy = nXy; Xz = nXz;
        Vx = nVx; Vy = nVy; Vz = nVz;
        Wx = nWx; Wy = nWy; Wz = nWz;
        px = npx; py = npy; pz = npz;
        pvx = npvx; pvy = npvy; pvz = npvz;
        R00 = nR00; R01 = nR01; R02 = nR02;
        R10 = nR10; R11 = nR11; R12 = nR12;
        R20 = nR20; R21 = nR21; R22 = nR22;
    }
}

extern "C" void kernel_launch(void* const* d_in, const int* in_sizes, int n_in,
                              void* d_out, int out_size)
{
    const float* z_grid   = (const float*)d_in[0];
    const float* controls = (const float*)d_in[1];
    const float* rpts     = (const float*)d_in[2];
    const float* Iinv     = (const float*)d_in[3];
    float*       out      = (float*)d_out;

    int B = in_sizes[0] / GRIDN;          // 256
    int T = in_sizes[1] / (B * 2);        // 500

    size_t smem_bytes = (size_t)(GRIDN + 2 * T) * sizeof(float);
    cudaFuncSetAttribute(physics_kernel,
                         cudaFuncAttributeMaxDynamicSharedMemorySize,
                         (int)smem_bytes);

    physics_kernel<<<B, 128, smem_bytes>>>(z_grid, controls, rpts, Iinv, out, T);
}

// round 2
// speedup vs baseline: 1.3868x; 1.3868x over previous
#include <cuda_runtime.h>
#include <math.h>

#define HW      128
#define GRIDN   (HW*HW)
#define NPTS    16

#define D_MAXF  6.4f
#define KSTIFF  5000.0f
#define KDAMP   894.4271909999159f   /* sqrt(4*40*5000) */
#define KFRIC   0.5f
#define MGRAV   392.40000000000003f  /* MASS*G */
#define DTF     0.01f
#define EPSF    1e-6f

__device__ __forceinline__ float clampidx(float q) {
    float v = (q + D_MAXF) * 10.0f;            /* == /GRID_RES, +-1ulp */
    return fminf(fmaxf(v, 0.0f), 126.0f);
}

__device__ __forceinline__ float bilin(const float* __restrict__ g, float xi, float yi) {
    float x0f = floorf(xi), y0f = floorf(yi);
    int   x0  = (int)x0f,   y0  = (int)y0f;
    float wx  = xi - x0f,   wy  = yi - y0f;
    const float* r = g + (x0 * HW + y0);
    float z00 = r[0], z01 = r[1], z10 = r[HW], z11 = r[HW + 1];
    return z00 * (1.0f - wx) * (1.0f - wy)
         + z10 * wx          * (1.0f - wy)
         + z01 * (1.0f - wx) * wy
         + z11 * wx          * wy;
}

__device__ __forceinline__ float rk4s(float x, float v, float dt) {
    float k1 = dt * v;
    float k2 = dt * (v + k1 * 0.5f);
    float k3 = dt * (v + k2 * 0.5f);
    float k4 = dt * (v + k3);
    return x + (k1 + 2.0f * k2 + 2.0f * k3 + k4) * (1.0f / 6.0f);
}

__device__ __forceinline__ float rsum16(float v) {
    v += __shfl_xor_sync(0xffffffffu, v, 1);
    v += __shfl_xor_sync(0xffffffffu, v, 2);
    v += __shfl_xor_sync(0xffffffffu, v, 4);
    v += __shfl_xor_sync(0xffffffffu, v, 8);
    return v;
}

/* tanh via MUFU exp: 1 - 2/(e^{2x}+1), ~1e-6 rel err, saturates cleanly */
__device__ __forceinline__ float ftanh(float x) {
    float xc = fminf(fmaxf(x, -15.0f), 15.0f);
    float e  = __expf(2.0f * xc);
    return 1.0f - __fdividef(2.0f, e + 1.0f);
}

__global__ void __launch_bounds__(128, 1)
physics_kernel(const float* __restrict__ z_grid,
               const float* __restrict__ controls,
               const float* __restrict__ rpts,
               const float* __restrict__ Iinv,
               float* __restrict__ out,
               int T)
{
    extern __shared__ float smem[];
    float* sg = smem;            // HW*HW terrain
    float* sc = smem + GRIDN;    // 2*T controls

    const int b   = blockIdx.x;
    const int tid = threadIdx.x;

    {
        const float4* src = reinterpret_cast<const float4*>(z_grid + (size_t)b * GRIDN);
        float4*       dst = reinterpret_cast<float4*>(sg);
        #pragma unroll 4
        for (int i = tid; i < GRIDN / 4; i += 128) dst[i] = src[i];
        const float* cs = controls + (size_t)b * T * 2;
        for (int i = tid; i < T * 2; i += 128) sc[i] = cs[i];
    }
    __syncthreads();
    if (tid >= 32) return;

    const int  lane = tid;
    const int  p    = lane & 15;
    const bool act  = lane < 16;

    float rpx = rpts[3 * p + 0], rpy = rpts[3 * p + 1], rpz = rpts[3 * p + 2];

    float my = rsum16(rpy) * (1.0f / 16.0f);
    const bool isL = rpy > my;
    const bool isR = rpy < my;

    const float I00 = Iinv[0], I01 = Iinv[1], I02 = Iinv[2];
    const float I10 = Iinv[3], I11 = Iinv[4], I12 = Iinv[5];
    const float I20 = Iinv[6], I21 = Iinv[7], I22 = Iinv[8];

    float Xx = 0.f, Xy = 0.f, Xz = 1.f;
    float Vx = 0.f, Vy = 0.f, Vz = 0.f;
    float Wx = 0.f, Wy = 0.f, Wz = 0.f;
    float R00 = 1.f, R01 = 0.f, R02 = 0.f;
    float R10 = 0.f, R11 = 1.f, R12 = 0.f;
    float R20 = 0.f, R21 = 0.f, R22 = 1.f;
    float px = rpx, py = rpy, pz = 1.0f + rpz;
    float pvx = 0.f, pvy = 0.f, pvz = 0.f;

    float* outb = out + (size_t)b * T * 162;

    for (int t = 0; t < T; ++t) {
        float ul = sc[2 * t], ur = sc[2 * t + 1];

        /* r-vector (old state) — needed both for torque and for the
           force-independent point-position update, so compute first */
        float rx = px - Xx, ry = py - Xy, rz = pz - Xz;

        /* point velocity & next point position: depend only on OLD state,
           independent of this step's forces -> schedule early */
        float npvx = Vx + (Wy * rz - Wz * ry);
        float npvy = Vy + (Wz * rx - Wx * rz);
        float npvz = Vz + (Wx * ry - Wy * rx);
        float npx = rk4s(px, npvx, DTF);
        float npy = rk4s(py, npvy, DTF);
        float npz = rk4s(pz, npvz, DTF);

        /* --- terrain sampling at current point --- */
        float xic = clampidx(px),          yic = clampidx(py);
        float xip = clampidx(px + 0.1f),   xim = clampidx(px - 0.1f);
        float yip = clampidx(py + 0.1f),   yim = clampidx(py - 0.1f);
        float z   = bilin(sg, xic, yic);
        float zxp = bilin(sg, xip, yic);
        float zxm = bilin(sg, xim, yic);
        float zyp = bilin(sg, xic, yip);
        float zym = bilin(sg, xic, yim);

        float dh = pz - z;
        bool  on = (px >= -D_MAXF) && (px <= D_MAXF) &&
                   (py >= -D_MAXF) && (py <= D_MAXF);
        float contact = (dh <= 0.0f && on) ? 1.0f : 0.0f;

        /* --- surface normal (reciprocal-multiply) --- */
        float dzdx = (zxp - zxm) * 5.0f;      /* == /0.2 */
        float dzdy = (zyp - zym) * 5.0f;
        float nx = -dzdx, ny = -dzdy, nz = 1.0f;
        float nn  = sqrtf(nx * nx + ny * ny + nz * nz) + EPSF;
        float rnn = __fdividef(1.0f, nn);
        nx *= rnn; ny *= rnn; nz *= rnn;

        /* --- spring/damper --- */
        float xdn = pvx * nx + pvy * ny + pvz * nz;
        float fm  = -(KSTIFF * dh + KDAMP * xdn) * contact;
        float Fsx = fm * nx;
        float Fsy = fm * ny;
        float Fsz = fm * nz;

        /* --- thrust = normalized col0 of R --- */
        float tnv = sqrtf(R00 * R00 + R10 * R10 + R20 * R20) + EPSF;
        float rtn = __fdividef(1.0f, tnv);
        float tx = R00 * rtn, ty = R10 * rtn, tz = R20 * rtn;

        /* --- friction --- */
        float Nn = sqrtf(Fsx * Fsx + Fsy * Fsy + Fsz * Fsz);
        float kN = KFRIC * Nn;
        float us = isL ? ul : ur;
        bool  lr = isL || isR;
        float Ffx = lr ? kN * ftanh(us * tx - pvx) : 0.0f;
        float Ffy = lr ? kN * ftanh(us * ty - pvy) : 0.0f;
        float Ffz = lr ? kN * ftanh(us * tz - pvz) : 0.0f;

        /* --- reductions --- */
        float Ftx = Fsx + Ffx, Fty = Fsy + Ffy, Ftz = Fsz + Ffz;
        float tqx = ry * Ftz - rz * Fty;
        float tqy = rz * Ftx - rx * Ftz;
        float tqz = rx * Fty - ry * Ftx;

        float Tqx  = rsum16(tqx), Tqy  = rsum16(tqy), Tqz  = rsum16(tqz);
        float SFsx = rsum16(Fsx), SFsy = rsum16(Fsy), SFsz = rsum16(Fsz);
        float SFfx = rsum16(Ffx), SFfy = rsum16(Ffy), SFfz = rsum16(Ffz);

        float odx = Tqx * I00 + Tqy * I01 + Tqz * I02;
        float ody = Tqx * I10 + Tqy * I11 + Tqz * I12;
        float odz = Tqx * I20 + Tqy * I21 + Tqz * I22;

        float Fcx = SFsx * (1.0f / 16.0f) + SFfx * (1.0f / 16.0f);
        float Fcy = SFsy * (1.0f / 16.0f) + SFfy * (1.0f / 16.0f);
        float Fcz = -MGRAV + SFsz * (1.0f / 16.0f) + SFfz * (1.0f / 16.0f);
        float ax = Fcx * 0.025f, ay = Fcy * 0.025f, az = Fcz * 0.025f;  /* /40 */

        /* --- integrate --- */
        float nVx = rk4s(Vx, ax, DTF), nVy = rk4s(Vy, ay, DTF), nVz = rk4s(Vz, az, DTF);
        float nXx = rk4s(Xx, nVx, DTF), nXy = rk4s(Xy, nVy, DTF), nXz = rk4s(Xz, nVz, DTF);
        float nWx = rk4s(Wx, odx, DTF), nWy = rk4s(Wy, ody, DTF), nWz = rk4s(Wz, odz, DTF);

        /* --- rotation update (Rodrigues) --- */
        float th = sqrtf(nWx * nWx + nWy * nWy + nWz * nWz);
        float rd = __fdividef(1.0f, th + EPSF);
        float wx = nWx * rd, wy = nWy * rd, wz = nWz * rd;
        float s, cth;
        __sincosf(th * DTF, &s, &cth);
        float c = 1.0f - cth;

        /* K = skew(w); Q = K*K expanded with K's zero diagonal */
        float Q00 = -(wz * wz + wy * wy);
        float Q01 = wy * wx;            /* (-wz)*0? careful: use full form */
        /* full Q = K@K for K=[[0,-wz,wy],[wz,0,-wx],[-wy,wx,0]] */
        Q00 = (-wz) * wz + wy * (-wy);
        Q01 = wy * wx;
        float Q02 = wz * wx;
        float Q10 = wx * wy;
        float Q11 = wz * (-wz) + (-wx) * wx;
        float Q12 = wz * wy;
        float Q20 = wx * wz;
        float Q21 = wy * wz;
        float Q22 = (-wy) * wy + wx * (-wx);

        float A00 = 1.0f + Q00 * c;
        float A01 = (-wz) * s + Q01 * c;
        float A02 =   wy  * s + Q02 * c;
        float A10 =   wz  * s + Q10 * c;
        float A11 = 1.0f + Q11 * c;
        float A12 = (-wx) * s + Q12 * c;
        float A20 = (-wy) * s + Q20 * c;
        float A21 =   wx  * s + Q21 * c;
        float A22 = 1.0f + Q22 * c;

        float nR00 = R00*A00 + R01*A10 + R02*A20;
        float nR01 = R00*A01 + R01*A11 + R02*A21;
        float nR02 = R00*A02 + R01*A12 + R02*A22;
        float nR10 = R10*A00 + R11*A10 + R12*A20;
        float nR11 = R10*A01 + R11*A11 + R12*A21;
        float nR12 = R10*A02 + R11*A12 + R12*A22;
        float nR20 = R20*A00 + R21*A10 + R22*A20;
        float nR21 = R20*A01 + R21*A11 + R22*A21;
        float nR22 = R20*A02 + R21*A12 + R22*A22;

        /* --- outputs --- */
        float* o = outb + (size_t)t * 162;
        if (lane == 0) {
            o[0] = nXx;  o[1] = nXy;  o[2] = nXz;
            o[3] = nVx;  o[4] = nVy;  o[5] = nVz;
            o[6] = nWx;  o[7] = nWy;  o[8] = nWz;
            o[9]  = nR00; o[10] = nR01; o[11] = nR02;
            o[12] = nR10; o[13] = nR11; o[14] = nR12;
            o[15] = nR20; o[16] = nR21; o[17] = nR22;
        }
        if (act) {
            o[18  + 3 * p] = npx; o[19  + 3 * p] = npy; o[20  + 3 * p] = npz;
            o[66  + 3 * p] = Fsx; o[67  + 3 * p] = Fsy; o[68  + 3 * p] = Fsz;
            o[114 + 3 * p] = Ffx; o[115 + 3 * p] = Ffy; o[116 + 3 * p] = Ffz;
        }

        /* --- commit --- */
        Xx = nXx; Xy = nXy; Xz = nXz;
        Vx = nVx; Vy = nVy; Vz = nVz;
        Wx = nWx; Wy = nWy; Wz = nWz;
        px = npx; py = npy; pz = npz;
        pvx = npvx; pvy = npvy; pvz = npvz;
        R00 = nR00; R01 = nR01; R02 = nR02;
        R10 = nR10; R11 = nR11; R12 = nR12;
        R20 = nR20; R21 = nR21; R22 = nR22;
    }
}

extern "C" void kernel_launch(void* const* d_in, const int* in_sizes, int n_in,
                              void* d_out, int out_size)
{
    const float* z_grid   = (const float*)d_in[0];
    const float* controls = (const float*)d_in[1];
    const float* rpts     = (const float*)d_in[2];
    const float* Iinv     = (const float*)d_in[3];
    float*       out      = (float*)d_out;

    int B = in_sizes[0] / GRIDN;
    int T = in_sizes[1] / (B * 2);

    size_t smem_bytes = (size_t)(GRIDN + 2 * T) * sizeof(float);
    cudaFuncSetAttribute(physics_kernel,
                         cudaFuncAttributeMaxDynamicSharedMemorySize,
                         (int)smem_bytes);

    physics_kernel<<<B, 128, smem_bytes>>>(z_grid, controls, rpts, Iinv, out, T);
}

// round 3
// speedup vs baseline: 2.2937x; 1.6540x over previous
#include <cuda_runtime.h>
#include <math.h>

#define HW      128
#define GRIDN   (HW*HW)

#define D_MAXF  6.4f
#define KSTIFF  5000.0f
#define KDAMP   894.4271909999159f   /* sqrt(4*40*5000) */
#define KFRIC   0.5f
#define MGRAV   392.40000000000003f  /* MASS*G */
#define DTF     0.01f
#define EPSF    1e-6f
/* RK4 with constant derivative collapses to x + v*RK4C:
   RK4C = dt*(6 + 3dt + dt^2 + dt^3/4)/6 for dt=0.01 */
#define RK4C    0.01005016666708333f

__device__ __forceinline__ float clampidx(float q) {
    float v = (q + D_MAXF) * 10.0f;
    return fminf(fmaxf(v, 0.0f), 126.0f);
}

__device__ __forceinline__ float bilin(const float* __restrict__ g, float xi, float yi) {
    float x0f = floorf(xi), y0f = floorf(yi);
    int   x0  = (int)x0f,   y0  = (int)y0f;
    float wx  = xi - x0f,   wy  = yi - y0f;
    const float* r = g + (x0 * HW + y0);
    float z00 = r[0], z01 = r[1], z10 = r[HW], z11 = r[HW + 1];
    return z00 * (1.0f - wx) * (1.0f - wy)
         + z10 * wx          * (1.0f - wy)
         + z01 * (1.0f - wx) * wy
         + z11 * wx          * wy;
}

__device__ __forceinline__ float rsum16(float v) {
    /* xor distances 1,2,4,8 stay within each 16-lane half-warp */
    v += __shfl_xor_sync(0xffffffffu, v, 1);
    v += __shfl_xor_sync(0xffffffffu, v, 2);
    v += __shfl_xor_sync(0xffffffffu, v, 4);
    v += __shfl_xor_sync(0xffffffffu, v, 8);
    return v;
}

__device__ __forceinline__ float ftanh(float x) {
    float xc = fminf(fmaxf(x, -15.0f), 15.0f);
    float e  = __expf(2.0f * xc);
    return 1.0f - __fdividef(2.0f, e + 1.0f);
}

__global__ void __launch_bounds__(128, 1)
physics_kernel(const float* __restrict__ z_grid,
               const float* __restrict__ controls,
               const float* __restrict__ rpts,
               const float* __restrict__ Iinv,
               float* __restrict__ out,
               int B, int T)
{
    extern __shared__ float smem[];
    float* sg = smem;              // 2 * GRIDN terrain (batch A, batch B)
    float* sc = smem + 2 * GRIDN;  // 4 * T controls (batch A, batch B)

    const int blk = blockIdx.x;
    const int tid = threadIdx.x;
    const int bA  = 2 * blk;
    const int bB  = (2 * blk + 1 < B) ? (2 * blk + 1) : (B - 1);

    /* Stage both terrains + both control tracks (contiguous in gmem). */
    {
        const float4* srcA = reinterpret_cast<const float4*>(z_grid + (size_t)bA * GRIDN);
        const float4* srcB = reinterpret_cast<const float4*>(z_grid + (size_t)bB * GRIDN);
        float4* dstA = reinterpret_cast<float4*>(sg);
        float4* dstB = reinterpret_cast<float4*>(sg + GRIDN);
        #pragma unroll 4
        for (int i = tid; i < GRIDN / 4; i += 128) { dstA[i] = srcA[i]; dstB[i] = srcB[i]; }
        const float* csA = controls + (size_t)bA * T * 2;
        const float* csB = controls + (size_t)bB * T * 2;
        for (int i = tid; i < T * 2; i += 128) { sc[i] = csA[i]; sc[2 * T + i] = csB[i]; }
    }
    __syncthreads();
    if (tid >= 32) return;        // single sim warp; lanes 0-15 batch A, 16-31 batch B

    const int  lane = tid;
    const int  half = lane >> 4;       // 0 = batch A, 1 = batch B
    const int  p    = lane & 15;
    const float* g  = sg + half * GRIDN;
    const float* cs = sc + half * 2 * T;

    float rpx = rpts[3 * p + 0], rpy = rpts[3 * p + 1], rpz = rpts[3 * p + 2];

    float my = rsum16(rpy) * (1.0f / 16.0f);
    const bool isL = rpy > my;
    const bool isR = rpy < my;

    const float I00 = Iinv[0], I01 = Iinv[1], I02 = Iinv[2];
    const float I10 = Iinv[3], I11 = Iinv[4], I12 = Iinv[5];
    const float I20 = Iinv[6], I21 = Iinv[7], I22 = Iinv[8];

    float Xx = 0.f, Xy = 0.f, Xz = 1.f;
    float Vx = 0.f, Vy = 0.f, Vz = 0.f;
    float Wx = 0.f, Wy = 0.f, Wz = 0.f;
    float R00 = 1.f, R01 = 0.f, R02 = 0.f;
    float R10 = 0.f, R11 = 1.f, R12 = 0.f;
    float R20 = 0.f, R21 = 0.f, R22 = 1.f;
    float px = rpx, py = rpy, pz = 1.0f + rpz;
    float pvx = 0.f, pvy = 0.f, pvz = 0.f;

    float* outb = out + (size_t)(half ? bB : bA) * T * 162;

    for (int t = 0; t < T; ++t) {
        float ul = cs[2 * t], ur = cs[2 * t + 1];

        float rx = px - Xx, ry = py - Xy, rz = pz - Xz;

        /* force-independent point update (old state) */
        float npvx = Vx + (Wy * rz - Wz * ry);
        float npvy = Vy + (Wz * rx - Wx * rz);
        float npvz = Vz + (Wx * ry - Wy * rx);
        float npx = fmaf(npvx, RK4C, px);
        float npy = fmaf(npvy, RK4C, py);
        float npz = fmaf(npvz, RK4C, pz);

        /* terrain */
        float xic = clampidx(px),        yic = clampidx(py);
        float xip = clampidx(px + 0.1f), xim = clampidx(px - 0.1f);
        float yip = clampidx(py + 0.1f), yim = clampidx(py - 0.1f);
        float z   = bilin(g, xic, yic);
        float zxp = bilin(g, xip, yic);
        float zxm = bilin(g, xim, yic);
        float zyp = bilin(g, xic, yip);
        float zym = bilin(g, xic, yim);

        float dh = pz - z;
        bool  on = (px >= -D_MAXF) && (px <= D_MAXF) &&
                   (py >= -D_MAXF) && (py <= D_MAXF);
        float contact = (dh <= 0.0f && on) ? 1.0f : 0.0f;

        /* normal */
        float dzdx = (zxp - zxm) * 5.0f;
        float dzdy = (zyp - zym) * 5.0f;
        float nx = -dzdx, ny = -dzdy, nz = 1.0f;
        float nn  = sqrtf(nx * nx + ny * ny + nz * nz) + EPSF;
        float rnn = __fdividef(1.0f, nn);
        nx *= rnn; ny *= rnn; nz *= rnn;

        /* spring/damper */
        float xdn = pvx * nx + pvy * ny + pvz * nz;
        float fm  = -(KSTIFF * dh + KDAMP * xdn) * contact;
        float Fsx = fm * nx, Fsy = fm * ny, Fsz = fm * nz;

        /* thrust */
        float tnv = sqrtf(R00 * R00 + R10 * R10 + R20 * R20) + EPSF;
        float rtn = __fdividef(1.0f, tnv);
        float tx = R00 * rtn, ty = R10 * rtn, tz = R20 * rtn;

        /* friction */
        float Nn = sqrtf(Fsx * Fsx + Fsy * Fsy + Fsz * Fsz);
        float kN = KFRIC * Nn;
        float us = isL ? ul : ur;
        bool  lr = isL || isR;
        float Ffx = lr ? kN * ftanh(us * tx - pvx) : 0.0f;
        float Ffy = lr ? kN * ftanh(us * ty - pvy) : 0.0f;
        float Ffz = lr ? kN * ftanh(us * tz - pvz) : 0.0f;

        /* reductions (within each 16-lane half) */
        float Ftx = Fsx + Ffx, Fty = Fsy + Ffy, Ftz = Fsz + Ffz;
        float tqx = ry * Ftz - rz * Fty;
        float tqy = rz * Ftx - rx * Ftz;
        float tqz = rx * Fty - ry * Ftx;

        float Tqx  = rsum16(tqx), Tqy  = rsum16(tqy), Tqz  = rsum16(tqz);
        float SFsx = rsum16(Fsx), SFsy = rsum16(Fsy), SFsz = rsum16(Fsz);
        float SFfx = rsum16(Ffx), SFfy = rsum16(Ffy), SFfz = rsum16(Ffz);

        float odx = Tqx * I00 + Tqy * I01 + Tqz * I02;
        float ody = Tqx * I10 + Tqy * I11 + Tqz * I12;
        float odz = Tqx * I20 + Tqy * I21 + Tqz * I22;

        float Fcx = SFsx * (1.0f / 16.0f) + SFfx * (1.0f / 16.0f);
        float Fcy = SFsy * (1.0f / 16.0f) + SFfy * (1.0f / 16.0f);
        float Fcz = -MGRAV + SFsz * (1.0f / 16.0f) + SFfz * (1.0f / 16.0f);
        float ax = Fcx * 0.025f, ay = Fcy * 0.025f, az = Fcz * 0.025f;

        /* integrate (collapsed RK4) */
        float nVx = fmaf(ax, RK4C, Vx), nVy = fmaf(ay, RK4C, Vy), nVz = fmaf(az, RK4C, Vz);
        float nXx = fmaf(nVx, RK4C, Xx), nXy = fmaf(nVy, RK4C, Xy), nXz = fmaf(nVz, RK4C, Xz);
        float nWx = fmaf(odx, RK4C, Wx), nWy = fmaf(ody, RK4C, Wy), nWz = fmaf(odz, RK4C, Wz);

        /* rotation (Rodrigues) */
        float th = sqrtf(nWx * nWx + nWy * nWy + nWz * nWz);
        float rd = __fdividef(1.0f, th + EPSF);
        float wx = nWx * rd, wy = nWy * rd, wz = nWz * rd;
        float s, cth;
        __sincosf(th * DTF, &s, &cth);
        float c = 1.0f - cth;

        float Q00 = (-wz) * wz + wy * (-wy);
        float Q01 = wy * wx;
        float Q02 = wz * wx;
        float Q10 = wx * wy;
        float Q11 = wz * (-wz) + (-wx) * wx;
        float Q12 = wz * wy;
        float Q20 = wx * wz;
        float Q21 = wy * wz;
        float Q22 = (-wy) * wy + wx * (-wx);

        float A00 = 1.0f + Q00 * c;
        float A01 = (-wz) * s + Q01 * c;
        float A02 =   wy  * s + Q02 * c;
        float A10 =   wz  * s + Q10 * c;
        float A11 = 1.0f + Q11 * c;
        float A12 = (-wx) * s + Q12 * c;
        float A20 = (-wy) * s + Q20 * c;
        float A21 =   wx  * s + Q21 * c;
        float A22 = 1.0f + Q22 * c;

        float nR00 = R00*A00 + R01*A10 + R02*A20;
        float nR01 = R00*A01 + R01*A11 + R02*A21;
        float nR02 = R00*A02 + R01*A12 + R02*A22;
        float nR10 = R10*A00 + R11*A10 + R12*A20;
        float nR11 = R10*A01 + R11*A11 + R12*A21;
        float nR12 = R10*A02 + R11*A12 + R12*A22;
        float nR20 = R20*A00 + R21*A10 + R22*A20;
        float nR21 = R20*A01 + R21*A11 + R22*A21;
        float nR22 = R20*A02 + R21*A12 + R22*A22;

        /* outputs */
        float* o = outb + (size_t)t * 162;
        if (p == 0) {   /* lane 0 (batch A) and lane 16 (batch B) */
            o[0] = nXx;  o[1] = nXy;  o[2] = nXz;
            o[3] = nVx;  o[4] = nVy;  o[5] = nVz;
            o[6] = nWx;  o[7] = nWy;  o[8] = nWz;
            o[9]  = nR00; o[10] = nR01; o[11] = nR02;
            o[12] = nR10; o[13] = nR11; o[14] = nR12;
            o[15] = nR20; o[16] = nR21; o[17] = nR22;
        }
        o[18  + 3 * p] = npx; o[19  + 3 * p] = npy; o[20  + 3 * p] = npz;
        o[66  + 3 * p] = Fsx; o[67  + 3 * p] = Fsy; o[68  + 3 * p] = Fsz;
        o[114 + 3 * p] = Ffx; o[115 + 3 * p] = Ffy; o[116 + 3 * p] = Ffz;

        /* commit */
        Xx = nXx; Xy = nXy; Xz = nXz;
        Vx = nVx; Vy = nVy; Vz = nVz;
        Wx = nWx; Wy = nWy; Wz = nWz;
        px = npx; py = npy; pz = npz;
        pvx = npvx; pvy = npvy; pvz = npvz;
        R00 = nR00; R01 = nR01; R02 = nR02;
        R10 = nR10; R11 = nR11; R12 = nR12;
        R20 = nR20; R21 = nR21; R22 = nR22;
    }
}

extern "C" void kernel_launch(void* const* d_in, const int* in_sizes, int n_in,
                              void* d_out, int out_size)
{
    const float* z_grid   = (const float*)d_in[0];
    const float* controls = (const float*)d_in[1];
    const float* rpts     = (const float*)d_in[2];
    const float* Iinv     = (const float*)d_in[3];
    float*       out      = (float*)d_out;

    int B = in_sizes[0] / GRIDN;          // 256
    int T = in_sizes[1] / (B * 2);        // 500

    int nblk = (B + 1) / 2;               // 128
    size_t smem_bytes = (size_t)(2 * GRIDN + 4 * T) * sizeof(float);
    cudaFuncSetAttribute(physics_kernel,
                         cudaFuncAttributeMaxDynamicSharedMemorySize,
                         (int)smem_bytes);

    physics_kernel<<<nblk, 128, smem_bytes>>>(z_grid, controls, rpts, Iinv, out, B, T);
}

// round 4
// speedup vs baseline: 2.8521x; 1.2435x over previous
#include <cuda_runtime.h>
#include <math.h>

#define HW      128
#define GRIDN   (HW*HW)

#define D_MAXF  6.4f
#define KSTIFF  5000.0f
#define KDAMP   894.4271909999159f
#define KFRIC   0.5f
#define MGRAV   392.40000000000003f
#define DTF     0.01f
#define RK4C    0.01005016666708333f   /* collapsed RK4, dt=0.01 */

__device__ __forceinline__ float clampi(float v) {
    return fminf(fmaxf(v, 0.0f), 126.0f);
}

/* lerp-form bilinear on shared-memory grid */
__device__ __forceinline__ float bilin(const float* __restrict__ g, float xi, float yi) {
    float x0f = floorf(xi), y0f = floorf(yi);
    int   x0  = (int)x0f,   y0  = (int)y0f;
    float wx  = xi - x0f,   wy  = yi - y0f;
    const float* r = g + (x0 * HW + y0);
    float a = r[0], b = r[1], c = r[HW], d = r[HW + 1];
    float z0 = fmaf(wx, c - a, a);
    float z1 = fmaf(wx, d - b, b);
    return fmaf(wy, z1 - z0, z0);
}

__device__ __forceinline__ float rsum16(float v) {
    v += __shfl_xor_sync(0xffffffffu, v, 1);
    v += __shfl_xor_sync(0xffffffffu, v, 2);
    v += __shfl_xor_sync(0xffffffffu, v, 4);
    v += __shfl_xor_sync(0xffffffffu, v, 8);
    return v;
}

__device__ __forceinline__ float ftanh(float x) {
    float xc = fminf(fmaxf(x, -15.0f), 15.0f);
    float e  = __expf(2.0f * xc);
    return 1.0f - __fdividef(2.0f, e + 1.0f);
}

__global__ void __launch_bounds__(128, 1)
physics_kernel(const float* __restrict__ z_grid,
               const float* __restrict__ controls,
               const float* __restrict__ rpts,
               const float* __restrict__ Iinv,
               float* __restrict__ out,
               int B, int T)
{
    extern __shared__ float smem[];
    float* sg = smem;
    float* sc = smem + 2 * GRIDN;

    const int blk = blockIdx.x;
    const int tid = threadIdx.x;
    const int bA  = 2 * blk;
    const int bB  = (2 * blk + 1 < B) ? (2 * blk + 1) : (B - 1);

    {
        const float4* srcA = reinterpret_cast<const float4*>(z_grid + (size_t)bA * GRIDN);
        const float4* srcB = reinterpret_cast<const float4*>(z_grid + (size_t)bB * GRIDN);
        float4* dstA = reinterpret_cast<float4*>(sg);
        float4* dstB = reinterpret_cast<float4*>(sg + GRIDN);
        #pragma unroll 4
        for (int i = tid; i < GRIDN / 4; i += 128) { dstA[i] = srcA[i]; dstB[i] = srcB[i]; }
        const float* csA = controls + (size_t)bA * T * 2;
        const float* csB = controls + (size_t)bB * T * 2;
        for (int i = tid; i < T * 2; i += 128) { sc[i] = csA[i]; sc[2 * T + i] = csB[i]; }
    }
    __syncthreads();
    if (tid >= 32) return;

    const int  lane = tid;
    const int  half = lane >> 4;
    const int  p    = lane & 15;
    const float*  g   = sg + half * GRIDN;
    const float2* cs2 = reinterpret_cast<const float2*>(sc + half * 2 * T);

    float rpx = rpts[3 * p + 0], rpy = rpts[3 * p + 1], rpz = rpts[3 * p + 2];

    float my = rsum16(rpy) * (1.0f / 16.0f);
    const bool isL = rpy > my;
    const bool isR = rpy < my;

    const float I00 = Iinv[0], I01 = Iinv[1], I02 = Iinv[2];
    const float I10 = Iinv[3], I11 = Iinv[4], I12 = Iinv[5];
    const float I20 = Iinv[6], I21 = Iinv[7], I22 = Iinv[8];

    float Xx = 0.f, Xy = 0.f, Xz = 1.f;
    float Vx = 0.f, Vy = 0.f, Vz = 0.f;
    float Wx = 0.f, Wy = 0.f, Wz = 0.f;
    float R00 = 1.f, R01 = 0.f, R02 = 0.f;
    float R10 = 0.f, R11 = 1.f, R12 = 0.f;
    float R20 = 0.f, R21 = 0.f, R22 = 1.f;
    float px = rpx, py = rpy, pz = 1.0f + rpz;
    float pvx = 0.f, pvy = 0.f, pvz = 0.f;

    float* outb = out + (size_t)(half ? bB : bA) * T * 162;

    for (int t = 0; t < T; ++t) {
        float2 u = cs2[t];

        float rx = px - Xx, ry = py - Xy, rz = pz - Xz;

        /* force-independent point update (old state) */
        float npvx = Vx + (Wy * rz - Wz * ry);
        float npvy = Vy + (Wz * rx - Wx * rz);
        float npvz = Vz + (Wx * ry - Wy * rx);
        float npx = fmaf(npvx, RK4C, px);
        float npy = fmaf(npvy, RK4C, py);
        float npz = fmaf(npvz, RK4C, pz);

        /* terrain: indices via single fma per variant (+-0.1 -> +-1 idx) */
        float xic = clampi(fmaf(px, 10.0f, 64.0f));
        float yic = clampi(fmaf(py, 10.0f, 64.0f));
        float xip = clampi(fmaf(px, 10.0f, 65.0f));
        float xim = clampi(fmaf(px, 10.0f, 63.0f));
        float yip = clampi(fmaf(py, 10.0f, 65.0f));
        float yim = clampi(fmaf(py, 10.0f, 63.0f));
        float z   = bilin(g, xic, yic);
        float zxp = bilin(g, xip, yic);
        float zxm = bilin(g, xim, yic);
        float zyp = bilin(g, xic, yip);
        float zym = bilin(g, xic, yim);

        float dh = pz - z;
        bool  on = (px >= -D_MAXF) && (px <= D_MAXF) &&
                   (py >= -D_MAXF) && (py <= D_MAXF);
        float contact = (dh <= 0.0f && on) ? 1.0f : 0.0f;

        /* normal: nz=1 -> |n| >= 1, EPS drop is <=1e-6 relative */
        float nx = (zxm - zxp) * 5.0f;
        float ny = (zym - zyp) * 5.0f;
        float rnn = rsqrtf(fmaf(nx, nx, fmaf(ny, ny, 1.0f)));
        float nnx = nx * rnn, nny = ny * rnn, nnz = rnn;

        /* spring/damper */
        float xdn = pvx * nnx + pvy * nny + pvz * nnz;
        float fm  = -(KSTIFF * dh + KDAMP * xdn) * contact;
        float Fsx = fm * nnx, Fsy = fm * nny, Fsz = fm * nnz;

        /* thrust: |R col0| ~= 1 */
        float rtn = rsqrtf(R00 * R00 + R10 * R10 + R20 * R20);
        float tx = R00 * rtn, ty = R10 * rtn, tz = R20 * rtn;

        /* friction */
        float s2 = Fsx * Fsx + Fsy * Fsy + Fsz * Fsz;
        float Nn = s2 * rsqrtf(fmaxf(s2, 1e-30f));
        float kN = KFRIC * Nn;
        float us = isL ? u.x : u.y;
        bool  lr = isL || isR;
        float Ffx = lr ? kN * ftanh(us * tx - pvx) : 0.0f;
        float Ffy = lr ? kN * ftanh(us * ty - pvy) : 0.0f;
        float Ffz = lr ? kN * ftanh(us * tz - pvz) : 0.0f;

        /* total force per point, torque; 6 reductions (Fc uses sum(Ft)) */
        float Ftx = Fsx + Ffx, Fty = Fsy + Ffy, Ftz = Fsz + Ffz;
        float tqx = ry * Ftz - rz * Fty;
        float tqy = rz * Ftx - rx * Ftz;
        float tqz = rx * Fty - ry * Ftx;

        float Tqx = rsum16(tqx), Tqy = rsum16(tqy), Tqz = rsum16(tqz);
        float SFx = rsum16(Ftx), SFy = rsum16(Fty), SFz = rsum16(Ftz);

        float odx = Tqx * I00 + Tqy * I01 + Tqz * I02;
        float ody = Tqx * I10 + Tqy * I11 + Tqz * I12;
        float odz = Tqx * I20 + Tqy * I21 + Tqz * I22;

        float ax = SFx * (0.025f / 16.0f);
        float ay = SFy * (0.025f / 16.0f);
        float az = fmaf(SFz, 0.025f / 16.0f, -MGRAV * 0.025f);

        /* integrate */
        float nVx = fmaf(ax, RK4C, Vx), nVy = fmaf(ay, RK4C, Vy), nVz = fmaf(az, RK4C, Vz);
        float nXx = fmaf(nVx, RK4C, Xx), nXy = fmaf(nVy, RK4C, Xy), nXz = fmaf(nVz, RK4C, Xz);
        float nWx = fmaf(odx, RK4C, Wx), nWy = fmaf(ody, RK4C, Wy), nWz = fmaf(odz, RK4C, Wz);

        /* Rodrigues */
        float ws  = nWx * nWx + nWy * nWy + nWz * nWz;
        float rws = rsqrtf(fmaxf(ws, 1e-30f));
        float th  = ws * rws;
        float wx = nWx * rws, wy = nWy * rws, wz = nWz * rws;
        float s, cth;
        __sincosf(th * DTF, &s, &cth);
        float c = 1.0f - cth;

        float Q01 = wy * wx, Q02 = wz * wx, Q12 = wz * wy;
        float Q00 = -(wz * wz + wy * wy);
        float Q11 = -(wz * wz + wx * wx);
        float Q22 = -(wy * wy + wx * wx);

        float A00 = 1.0f + Q00 * c;
        float A01 = fmaf(-wz, s, Q01 * c);
        float A02 = fmaf( wy, s, Q02 * c);
        float A10 = fmaf( wz, s, Q01 * c);
        float A11 = 1.0f + Q11 * c;
        float A12 = fmaf(-wx, s, Q12 * c);
        float A20 = fmaf(-wy, s, Q02 * c);
        float A21 = fmaf( wx, s, Q12 * c);
        float A22 = 1.0f + Q22 * c;

        float nR00 = R00*A00 + R01*A10 + R02*A20;
        float nR01 = R00*A01 + R01*A11 + R02*A21;
        float nR02 = R00*A02 + R01*A12 + R02*A22;
        float nR10 = R10*A00 + R11*A10 + R12*A20;
        float nR11 = R10*A01 + R11*A11 + R12*A21;
        float nR12 = R10*A02 + R11*A12 + R12*A22;
        float nR20 = R20*A00 + R21*A10 + R22*A20;
        float nR21 = R20*A01 + R21*A11 + R22*A21;
        float nR22 = R20*A02 + R21*A12 + R22*A22;

        /* outputs */
        float* o = outb + (size_t)t * 162;
        if (p == 0) {
            o[0] = nXx;  o[1] = nXy;  o[2] = nXz;
            o[3] = nVx;  o[4] = nVy;  o[5] = nVz;
            o[6] = nWx;  o[7] = nWy;  o[8] = nWz;
            o[9]  = nR00; o[10] = nR01; o[11] = nR02;
            o[12] = nR10; o[13] = nR11; o[14] = nR12;
            o[15] = nR20; o[16] = nR21; o[17] = nR22;
        }
        o[18  + 3 * p] = npx; o[19  + 3 * p] = npy; o[20  + 3 * p] = npz;
        o[66  + 3 * p] = Fsx; o[67  + 3 * p] = Fsy; o[68  + 3 * p] = Fsz;
        o[114 + 3 * p] = Ffx; o[115 + 3 * p] = Ffy; o[116 + 3 * p] = Ffz;

        /* commit */
        Xx = nXx; Xy = nXy; Xz = nXz;
        Vx = nVx; Vy = nVy; Vz = nVz;
        Wx = nWx; Wy = nWy; Wz = nWz;
        px = npx; py = npy; pz = npz;
        pvx = npvx; pvy = npvy; pvz = npvz;
        R00 = nR00; R01 = nR01; R02 = nR02;
        R10 = nR10; R11 = nR11; R12 = nR12;
        R20 = nR20; R21 = nR21; R22 = nR22;
    }
}

extern "C" void kernel_launch(void* const* d_in, const int* in_sizes, int n_in,
                              void* d_out, int out_size)
{
    const float* z_grid   = (const float*)d_in[0];
    const float* controls = (const float*)d_in[1];
    const float* rpts     = (const float*)d_in[2];
    const float* Iinv     = (const float*)d_in[3];
    float*       out      = (float*)d_out;

    int B = in_sizes[0] / GRIDN;
    int T = in_sizes[1] / (B * 2);

    int nblk = (B + 1) / 2;
    size_t smem_bytes = (size_t)(2 * GRIDN + 4 * T) * sizeof(float);
    cudaFuncSetAttribute(physics_kernel,
                         cudaFuncAttributeMaxDynamicSharedMemorySize,
                         (int)smem_bytes);

    physics_kernel<<<nblk, 128, smem_bytes>>>(z_grid, controls, rpts, Iinv, out, B, T);
}

// round 6
// speedup vs baseline: 3.2956x; 1.1555x over previous
#include <cuda_runtime.h>
#include <math.h>

#define HW      128
#define GRIDN   (HW*HW)

#define D_MAXF  6.4f
#define KSTIFF  5000.0f
#define KDAMP   894.4271909999159f
#define KFRIC   0.5f
#define MGRAV   392.40000000000003f
#define DTF     0.01f
#define RK4C    0.01005016666708333f   /* collapsed RK4, dt=0.01 */

__device__ __forceinline__ float clampi(float v) {
    return fminf(fmaxf(v, 0.0f), 126.0f);
}

__device__ __forceinline__ float bilin(const float* __restrict__ g, float xi, float yi) {
    float x0f = floorf(xi), y0f = floorf(yi);
    int   x0  = (int)x0f,   y0  = (int)y0f;
    float wx  = xi - x0f,   wy  = yi - y0f;
    const float* r = g + (x0 * HW + y0);
    float a = r[0], b = r[1], c = r[HW], d = r[HW + 1];
    float z0 = fmaf(wx, c - a, a);
    float z1 = fmaf(wx, d - b, b);
    return fmaf(wy, z1 - z0, z0);
}

/* 16-lane butterfly sum (xor 1,2,4,8 keeps each half-warp independent) */
__device__ __forceinline__ float rsum16(float v) {
    v += __shfl_xor_sync(0xffffffffu, v, 1);
    v += __shfl_xor_sync(0xffffffffu, v, 2);
    v += __shfl_xor_sync(0xffffffffu, v, 4);
    v += __shfl_xor_sync(0xffffffffu, v, 8);
    return v;
}

__device__ __forceinline__ float ftanh(float x) {
    float xc = fminf(fmaxf(x, -15.0f), 15.0f);
    float e  = __expf(2.0f * xc);
    return 1.0f - __fdividef(2.0f, e + 1.0f);
}

__global__ void __launch_bounds__(128, 1)
physics_kernel(const float* __restrict__ z_grid,
               const float* __restrict__ controls,
               const float* __restrict__ rpts,
               const float* __restrict__ Iinv,
               float* __restrict__ out,
               int B, int T)
{
    extern __shared__ float smem[];
    float* sg = smem;
    float* sc = smem + 2 * GRIDN;

    const int blk = blockIdx.x;
    const int tid = threadIdx.x;
    const int bA  = 2 * blk;
    const int bB  = (2 * blk + 1 < B) ? (2 * blk + 1) : (B - 1);

    {
        const float4* srcA = reinterpret_cast<const float4*>(z_grid + (size_t)bA * GRIDN);
        const float4* srcB = reinterpret_cast<const float4*>(z_grid + (size_t)bB * GRIDN);
        float4* dstA = reinterpret_cast<float4*>(sg);
        float4* dstB = reinterpret_cast<float4*>(sg + GRIDN);
        #pragma unroll 4
        for (int i = tid; i < GRIDN / 4; i += 128) { dstA[i] = srcA[i]; dstB[i] = srcB[i]; }
        const float* csA = controls + (size_t)bA * T * 2;
        const float* csB = controls + (size_t)bB * T * 2;
        for (int i = tid; i < T * 2; i += 128) { sc[i] = csA[i]; sc[2 * T + i] = csB[i]; }
    }
    __syncthreads();
    if (tid >= 32) return;

    const int     lane = tid;
    const int     half = lane >> 4;
    const int     p    = lane & 15;
    const float*  g    = sg + half * GRIDN;
    const float2* cs2  = reinterpret_cast<const float2*>(sc + half * 2 * T);

    float rpx = rpts[3 * p + 0], rpy = rpts[3 * p + 1], rpz = rpts[3 * p + 2];

    float my = rsum16(rpy) * (1.0f / 16.0f);
    const bool isL = rpy > my;
    const bool isR = rpy < my;

    const float I00 = Iinv[0], I01 = Iinv[1], I02 = Iinv[2];
    const float I10 = Iinv[3], I11 = Iinv[4], I12 = Iinv[5];
    const float I20 = Iinv[6], I21 = Iinv[7], I22 = Iinv[8];

    float Xx = 0.f, Xy = 0.f, Xz = 1.f;
    float Vx = 0.f, Vy = 0.f, Vz = 0.f;
    float Wx = 0.f, Wy = 0.f, Wz = 0.f;
    float R00 = 1.f, R01 = 0.f, R02 = 0.f;
    float R10 = 0.f, R11 = 1.f, R12 = 0.f;
    float R20 = 0.f, R21 = 0.f, R22 = 1.f;
    float px = rpx, py = rpy, pz = 1.0f + rpz;
    float pvx = 0.f, pvy = 0.f, pvz = 0.f;

    float* outb = out + (size_t)(half ? bB : bA) * T * 162;

    #pragma unroll 2
    for (int t = 0; t < T; ++t) {
        float2 u = cs2[t];

        float rx = px - Xx, ry = py - Xy, rz = pz - Xz;

        /* force-independent point update (old state) */
        float npvx = Vx + (Wy * rz - Wz * ry);
        float npvy = Vy + (Wz * rx - Wx * rz);
        float npvz = Vz + (Wx * ry - Wy * rx);
        float npx = fmaf(npvx, RK4C, px);
        float npy = fmaf(npvy, RK4C, py);
        float npz = fmaf(npvz, RK4C, pz);

        /* ---- terrain: z + finite-difference slopes ---- */
        float xi = fmaf(px, 10.0f, 64.0f);
        float yi = fmaf(py, 10.0f, 64.0f);
        float z, nx, ny;

        bool fastok = (xi >= 1.0f) && (xi <= 125.0f) &&
                      (yi >= 1.0f) && (yi <= 125.0f);
        if (__all_sync(0xffffffffu, fastok)) {
            /* interior: 5 queries share a 12-point stencil, common wx/wy */
            float x0f = floorf(xi), y0f = floorf(yi);
            int   x0  = (int)x0f,   y0  = (int)y0f;
            float wx  = xi - x0f,   wy  = yi - y0f;
            const float* r = g + ((x0 - 1) * HW + y0);
            float A0 = r[0],      B0 = r[1];
            float A1 = r[HW],     B1 = r[HW + 1];
            float A2 = r[2 * HW], B2 = r[2 * HW + 1];
            float A3 = r[3 * HW], B3 = r[3 * HW + 1];
            float C0 = r[HW - 1],     C1 = r[2 * HW - 1];
            float D0 = r[HW + 2],     D1 = r[2 * HW + 2];

            float zx0 = fmaf(wx, A2 - A1, A1);
            float zx1 = fmaf(wx, B2 - B1, B1);
            z         = fmaf(wy, zx1 - zx0, zx0);
            float zp0 = fmaf(wx, A3 - A2, A2);
            float zp1 = fmaf(wx, B3 - B2, B2);
            float zxp = fmaf(wy, zp1 - zp0, zp0);
            float zm0 = fmaf(wx, A1 - A0, A0);
            float zm1 = fmaf(wx, B1 - B0, B0);
            float zxm = fmaf(wy, zm1 - zm0, zm0);
            float zd  = fmaf(wx, D1 - D0, D0);
            float zyp = fmaf(wy, zd - zx1, zx1);
            float zc  = fmaf(wx, C1 - C0, C0);
            float zym = fmaf(wy, zx0 - zc, zc);

            nx = (zxm - zxp) * 5.0f;
            ny = (zym - zyp) * 5.0f;
        } else {
            /* edge: exact clamped per-query semantics */
            float xic = clampi(xi);
            float yic = clampi(yi);
            float xip = clampi(fmaf(px, 10.0f, 65.0f));
            float xim = clampi(fmaf(px, 10.0f, 63.0f));
            float yip = clampi(fmaf(py, 10.0f, 65.0f));
            float yim = clampi(fmaf(py, 10.0f, 63.0f));
            z         = bilin(g, xic, yic);
            float zxp = bilin(g, xip, yic);
            float zxm = bilin(g, xim, yic);
            float zyp = bilin(g, xic, yip);
            float zym = bilin(g, xic, yim);
            nx = (zxm - zxp) * 5.0f;
            ny = (zym - zyp) * 5.0f;
        }

        float dh = pz - z;
        bool  on = (px >= -D_MAXF) && (px <= D_MAXF) &&
                   (py >= -D_MAXF) && (py <= D_MAXF);
        float contact = (dh <= 0.0f && on) ? 1.0f : 0.0f;

        /* normal */
        float rnn = rsqrtf(fmaf(nx, nx, fmaf(ny, ny, 1.0f)));
        float nnx = nx * rnn, nny = ny * rnn, nnz = rnn;

        /* spring/damper */
        float xdn = pvx * nnx + pvy * nny + pvz * nnz;
        float fm  = -(KSTIFF * dh + KDAMP * xdn) * contact;
        float Fsx = fm * nnx, Fsy = fm * nny, Fsz = fm * nnz;

        /* thrust */
        float rtn = rsqrtf(R00 * R00 + R10 * R10 + R20 * R20);
        float tx = R00 * rtn, ty = R10 * rtn, tz = R20 * rtn;

        /* friction */
        float s2 = Fsx * Fsx + Fsy * Fsy + Fsz * Fsz;
        float Nn = s2 * rsqrtf(fmaxf(s2, 1e-30f));
        float kN = KFRIC * Nn;
        float us = isL ? u.x : u.y;
        bool  lr = isL || isR;
        float Ffx = lr ? kN * ftanh(us * tx - pvx) : 0.0f;
        float Ffy = lr ? kN * ftanh(us * ty - pvy) : 0.0f;
        float Ffz = lr ? kN * ftanh(us * tz - pvz) : 0.0f;

        /* totals, torque; 6 butterfly reductions */
        float Ftx = Fsx + Ffx, Fty = Fsy + Ffy, Ftz = Fsz + Ffz;
        float tqx = ry * Ftz - rz * Fty;
        float tqy = rz * Ftx - rx * Ftz;
        float tqz = rx * Fty - ry * Ftx;

        float Tqx = rsum16(tqx), Tqy = rsum16(tqy), Tqz = rsum16(tqz);
        float SFx = rsum16(Ftx), SFy = rsum16(Fty), SFz = rsum16(Ftz);

        float odx = Tqx * I00 + Tqy * I01 + Tqz * I02;
        float ody = Tqx * I10 + Tqy * I11 + Tqz * I12;
        float odz = Tqx * I20 + Tqy * I21 + Tqz * I22;

        float ax = SFx * (0.025f / 16.0f);
        float ay = SFy * (0.025f / 16.0f);
        float az = fmaf(SFz, 0.025f / 16.0f, -MGRAV * 0.025f);

        /* integrate */
        float nVx = fmaf(ax, RK4C, Vx), nVy = fmaf(ay, RK4C, Vy), nVz = fmaf(az, RK4C, Vz);
        float nXx = fmaf(nVx, RK4C, Xx), nXy = fmaf(nVy, RK4C, Xy), nXz = fmaf(nVz, RK4C, Xz);
        float nWx = fmaf(odx, RK4C, Wx), nWy = fmaf(ody, RK4C, Wy), nWz = fmaf(odz, RK4C, Wz);

        /* Rodrigues */
        float ws  = nWx * nWx + nWy * nWy + nWz * nWz;
        float rws = rsqrtf(fmaxf(ws, 1e-30f));
        float th  = ws * rws;
        float wxr = nWx * rws, wyr = nWy * rws, wzr = nWz * rws;
        float s, cth;
        __sincosf(th * DTF, &s, &cth);
        float c = 1.0f - cth;

        float Q01 = wyr * wxr, Q02 = wzr * wxr, Q12 = wzr * wyr;
        float Q00 = -(wzr * wzr + wyr * wyr);
        float Q11 = -(wzr * wzr + wxr * wxr);
        float Q22 = -(wyr * wyr + wxr * wxr);

        float A00 = 1.0f + Q00 * c;
        float A01 = fmaf(-wzr, s, Q01 * c);
        float A02 = fmaf( wyr, s, Q02 * c);
        float A10 = fmaf( wzr, s, Q01 * c);
        float A11 = 1.0f + Q11 * c;
        float A12 = fmaf(-wxr, s, Q12 * c);
        float A20 = fmaf(-wyr, s, Q02 * c);
        float A21 = fmaf( wxr, s, Q12 * c);
        float A22 = 1.0f + Q22 * c;

        float nR00 = R00*A00 + R01*A10 + R02*A20;
        float nR01 = R00*A01 + R01*A11 + R02*A21;
        float nR02 = R00*A02 + R01*A12 + R02*A22;
        float nR10 = R10*A00 + R11*A10 + R12*A20;
        float nR11 = R10*A01 + R11*A11 + R12*A21;
        float nR12 = R10*A02 + R11*A12 + R12*A22;
        float nR20 = R20*A00 + R21*A10 + R22*A20;
        float nR21 = R20*A01 + R21*A11 + R22*A21;
        float nR22 = R20*A02 + R21*A12 + R22*A22;

        /* outputs */
        float* o = outb + (size_t)t * 162;
        if (p == 0) {
            o[0] = nXx;  o[1] = nXy;  o[2] = nXz;
            o[3] = nVx;  o[4] = nVy;  o[5] = nVz;
            o[6] = nWx;  o[7] = nWy;  o[8] = nWz;
            o[9]  = nR00; o[10] = nR01; o[11] = nR02;
            o[12] = nR10; o[13] = nR11; o[14] = nR12;
            o[15] = nR20; o[16] = nR21; o[17] = nR22;
        }
        o[18  + 3 * p] = npx; o[19  + 3 * p] = npy; o[20  + 3 * p] = npz;
        o[66  + 3 * p] = Fsx; o[67  + 3 * p] = Fsy; o[68  + 3 * p] = Fsz;
        o[114 + 3 * p] = Ffx; o[115 + 3 * p] = Ffy; o[116 + 3 * p] = Ffz;

        /* commit */
        Xx = nXx; Xy = nXy; Xz = nXz;
        Vx = nVx; Vy = nVy; Vz = nVz;
        Wx = nWx; Wy = nWy; Wz = nWz;
        px = npx; py = npy; pz = npz;
        pvx = npvx; pvy = npvy; pvz = npvz;
        R00 = nR00; R01 = nR01; R02 = nR02;
        R10 = nR10; R11 = nR11; R12 = nR12;
        R20 = nR20; R21 = nR21; R22 = nR22;
    }
}

extern "C" void kernel_launch(void* const* d_in, const int* in_sizes, int n_in,
                              void* d_out, int out_size)
{
    const float* z_grid   = (const float*)d_in[0];
    const float* controls = (const float*)d_in[1];
    const float* rpts     = (const float*)d_in[2];
    const float* Iinv     = (const float*)d_in[3];
    float*       out      = (float*)d_out;

    int B = in_sizes[0] / GRIDN;
    int T = in_sizes[1] / (B * 2);

    int nblk = (B + 1) / 2;
    size_t smem_bytes = (size_t)(2 * GRIDN + 4 * T) * sizeof(float);
    cudaFuncSetAttribute(physics_kernel,
                         cudaFuncAttributeMaxDynamicSharedMemorySize,
                         (int)smem_bytes);

    physics_kernel<<<nblk, 128, smem_bytes>>>(z_grid, controls, rpts, Iinv, out, B, T);
}

// round 7
// speedup vs baseline: 3.7073x; 1.1249x over previous
#include <cuda_runtime.h>
#include <math.h>

#define HW      128
#define GRIDN   (HW*HW)

#define D_MAXF  6.4f
#define KSTIFF  5000.0f
#define KDAMP   894.4271909999159f
#define KFRIC   0.5f
#define MGRAV   392.40000000000003f
#define DTF     0.01f
#define DT2F    1e-4f
#define RK4C    0.01005016666708333f   /* collapsed RK4, dt=0.01 */

__device__ __forceinline__ float clampi(float v) {
    return fminf(fmaxf(v, 0.0f), 126.0f);
}

__device__ __forceinline__ float bilin(const float* __restrict__ g, float xi, float yi) {
    float x0f = floorf(xi), y0f = floorf(yi);
    int   x0  = (int)x0f,   y0  = (int)y0f;
    float wx  = xi - x0f,   wy  = yi - y0f;
    const float* r = g + (x0 * HW + y0);
    float a = r[0], b = r[1], c = r[HW], d = r[HW + 1];
    float z0 = fmaf(wx, c - a, a);
    float z1 = fmaf(wx, d - b, b);
    return fmaf(wy, z1 - z0, z0);
}

__device__ __forceinline__ float rsum16(float v) {
    v += __shfl_xor_sync(0xffffffffu, v, 1);
    v += __shfl_xor_sync(0xffffffffu, v, 2);
    v += __shfl_xor_sync(0xffffffffu, v, 4);
    v += __shfl_xor_sync(0xffffffffu, v, 8);
    return v;
}

__device__ __forceinline__ float ftanh(float x) {
    float xc = fminf(fmaxf(x, -15.0f), 15.0f);
    float e  = __expf(2.0f * xc);
    return 1.0f - __fdividef(2.0f, e + 1.0f);
}

__global__ void __launch_bounds__(128, 1)
physics_kernel(const float* __restrict__ z_grid,
               const float* __restrict__ controls,
               const float* __restrict__ rpts,
               const float* __restrict__ Iinv,
               float* __restrict__ out,
               int B, int T)
{
    extern __shared__ float smem[];
    float* sg = smem;
    float* sc = smem + 2 * GRIDN;

    const int blk = blockIdx.x;
    const int tid = threadIdx.x;
    const int bA  = 2 * blk;
    const int bB  = (2 * blk + 1 < B) ? (2 * blk + 1) : (B - 1);

    {
        const float4* srcA = reinterpret_cast<const float4*>(z_grid + (size_t)bA * GRIDN);
        const float4* srcB = reinterpret_cast<const float4*>(z_grid + (size_t)bB * GRIDN);
        float4* dstA = reinterpret_cast<float4*>(sg);
        float4* dstB = reinterpret_cast<float4*>(sg + GRIDN);
        #pragma unroll 4
        for (int i = tid; i < GRIDN / 4; i += 128) { dstA[i] = srcA[i]; dstB[i] = srcB[i]; }
        const float* csA = controls + (size_t)bA * T * 2;
        const float* csB = controls + (size_t)bB * T * 2;
        for (int i = tid; i < T * 2; i += 128) { sc[i] = csA[i]; sc[2 * T + i] = csB[i]; }
    }
    __syncthreads();
    if (tid >= 32) return;

    const int     lane = tid;
    const int     half = lane >> 4;
    const int     p    = lane & 15;
    const float*  g    = sg + half * GRIDN;
    const float2* cs2  = reinterpret_cast<const float2*>(sc + half * 2 * T);

    /* hoisted predicates for the store-select tree */
    const bool b0 = (p & 1), b1 = (p & 2), b2 = (p & 4), b3 = (p & 8);

    float rpx = rpts[3 * p + 0], rpy = rpts[3 * p + 1], rpz = rpts[3 * p + 2];

    float my = rsum16(rpy) * (1.0f / 16.0f);
    const bool isL = rpy > my;
    const bool isR = rpy < my;

    const float I00 = Iinv[0], I01 = Iinv[1], I02 = Iinv[2];
    const float I10 = Iinv[3], I11 = Iinv[4], I12 = Iinv[5];
    const float I20 = Iinv[6], I21 = Iinv[7], I22 = Iinv[8];

    float Xx = 0.f, Xy = 0.f, Xz = 1.f;
    float Vx = 0.f, Vy = 0.f, Vz = 0.f;
    float Wx = 0.f, Wy = 0.f, Wz = 0.f;
    float R00 = 1.f, R01 = 0.f, R02 = 0.f;
    float R10 = 0.f, R11 = 1.f, R12 = 0.f;
    float R20 = 0.f, R21 = 0.f, R22 = 1.f;
    float px = rpx, py = rpy, pz = 1.0f + rpz;
    float pvx = 0.f, pvy = 0.f, pvz = 0.f;

    float* outb = out + (size_t)(half ? bB : bA) * T * 162;

    #pragma unroll 2
    for (int t = 0; t < T; ++t) {
        float2 u = cs2[t];

        float rx = px - Xx, ry = py - Xy, rz = pz - Xz;

        /* force-independent point update (old state) */
        float npvx = Vx + (Wy * rz - Wz * ry);
        float npvy = Vy + (Wz * rx - Wx * rz);
        float npvz = Vz + (Wx * ry - Wy * rx);
        float npx = fmaf(npvx, RK4C, px);
        float npy = fmaf(npvy, RK4C, py);
        float npz = fmaf(npvz, RK4C, pz);

        /* ---- terrain ---- */
        float xi = fmaf(px, 10.0f, 64.0f);
        float yi = fmaf(py, 10.0f, 64.0f);
        float z, nx, ny;

        bool fastok = (xi >= 1.0f) && (xi <= 125.0f) &&
                      (yi >= 1.0f) && (yi <= 125.0f);
        if (__all_sync(0xffffffffu, fastok)) {
            float x0f = floorf(xi), y0f = floorf(yi);
            int   x0  = (int)x0f,   y0  = (int)y0f;
            float wx  = xi - x0f,   wy  = yi - y0f;
            const float* r = g + ((x0 - 1) * HW + y0);
            float A0 = r[0],      B0 = r[1];
            float A1 = r[HW],     B1 = r[HW + 1];
            float A2 = r[2 * HW], B2 = r[2 * HW + 1];
            float A3 = r[3 * HW], B3 = r[3 * HW + 1];
            float C0 = r[HW - 1],     C1 = r[2 * HW - 1];
            float D0 = r[HW + 2],     D1 = r[2 * HW + 2];

            float zx0 = fmaf(wx, A2 - A1, A1);
            float zx1 = fmaf(wx, B2 - B1, B1);
            z         = fmaf(wy, zx1 - zx0, zx0);
            float zp0 = fmaf(wx, A3 - A2, A2);
            float zp1 = fmaf(wx, B3 - B2, B2);
            float zxp = fmaf(wy, zp1 - zp0, zp0);
            float zm0 = fmaf(wx, A1 - A0, A0);
            float zm1 = fmaf(wx, B1 - B0, B0);
            float zxm = fmaf(wy, zm1 - zm0, zm0);
            float zd  = fmaf(wx, D1 - D0, D0);
            float zyp = fmaf(wy, zd - zx1, zx1);
            float zc  = fmaf(wx, C1 - C0, C0);
            float zym = fmaf(wy, zx0 - zc, zc);

            nx = (zxm - zxp) * 5.0f;
            ny = (zym - zyp) * 5.0f;
        } else {
            float xic = clampi(xi);
            float yic = clampi(yi);
            float xip = clampi(fmaf(px, 10.0f, 65.0f));
            float xim = clampi(fmaf(px, 10.0f, 63.0f));
            float yip = clampi(fmaf(py, 10.0f, 65.0f));
            float yim = clampi(fmaf(py, 10.0f, 63.0f));
            z         = bilin(g, xic, yic);
            float zxp = bilin(g, xip, yic);
            float zxm = bilin(g, xim, yic);
            float zyp = bilin(g, xic, yip);
            float zym = bilin(g, xic, yim);
            nx = (zxm - zxp) * 5.0f;
            ny = (zym - zyp) * 5.0f;
        }

        float dh = pz - z;
        bool  on = (px >= -D_MAXF) && (px <= D_MAXF) &&
                   (py >= -D_MAXF) && (py <= D_MAXF);
        float contact = (dh <= 0.0f && on) ? 1.0f : 0.0f;

        /* normal */
        float rnn = rsqrtf(fmaf(nx, nx, fmaf(ny, ny, 1.0f)));
        float nnx = nx * rnn, nny = ny * rnn, nnz = rnn;

        /* spring/damper; |F_spring| = |fm| since |n_hat| = 1 */
        float xdn = pvx * nnx + pvy * nny + pvz * nnz;
        float fm  = -(KSTIFF * dh + KDAMP * xdn) * contact;
        float Fsx = fm * nnx, Fsy = fm * nny, Fsz = fm * nnz;
        float kN  = KFRIC * fabsf(fm);

        /* thrust */
        float rtn = rsqrtf(R00 * R00 + R10 * R10 + R20 * R20);
        float tx = R00 * rtn, ty = R10 * rtn, tz = R20 * rtn;

        /* friction */
        float us = isL ? u.x : u.y;
        bool  lr = isL || isR;
        float Ffx = lr ? kN * ftanh(us * tx - pvx) : 0.0f;
        float Ffy = lr ? kN * ftanh(us * ty - pvy) : 0.0f;
        float Ffz = lr ? kN * ftanh(us * tz - pvz) : 0.0f;

        /* totals, torque; 6 butterfly reductions */
        float Ftx = Fsx + Ffx, Fty = Fsy + Ffy, Ftz = Fsz + Ffz;
        float tqx = ry * Ftz - rz * Fty;
        float tqy = rz * Ftx - rx * Ftz;
        float tqz = rx * Fty - ry * Ftx;

        float Tqx = rsum16(tqx), Tqy = rsum16(tqy), Tqz = rsum16(tqz);
        float SFx = rsum16(Ftx), SFy = rsum16(Fty), SFz = rsum16(Ftz);

        float odx = Tqx * I00 + Tqy * I01 + Tqz * I02;
        float ody = Tqx * I10 + Tqy * I11 + Tqz * I12;
        float odz = Tqx * I20 + Tqy * I21 + Tqz * I22;

        float ax = SFx * (0.025f / 16.0f);
        float ay = SFy * (0.025f / 16.0f);
        float az = fmaf(SFz, 0.025f / 16.0f, -MGRAV * 0.025f);

        /* integrate */
        float nVx = fmaf(ax, RK4C, Vx), nVy = fmaf(ay, RK4C, Vy), nVz = fmaf(az, RK4C, Vz);
        float nXx = fmaf(nVx, RK4C, Xx), nXy = fmaf(nVy, RK4C, Xy), nXz = fmaf(nVz, RK4C, Xz);
        float nWx = fmaf(odx, RK4C, Wx), nWy = fmaf(ody, RK4C, Wy), nWz = fmaf(odz, RK4C, Wz);

        /* Rodrigues via even polynomials in q = |w|^2 dt^2:
           sa = sin(th*dt)/th, ca = (1-cos(th*dt))/th^2, S = skew(nW) */
        float ws = nWx * nWx + nWy * nWy + nWz * nWz;
        float q  = ws * DT2F;
        float sa = DTF * fmaf(q, fmaf(q, fmaf(q, -1.0f/5040.0f, 1.0f/120.0f), -1.0f/6.0f), 1.0f);
        float ca = (0.5f * DT2F) *
                   fmaf(q, fmaf(q, fmaf(q, -1.0f/20160.0f, 1.0f/360.0f), -1.0f/12.0f), 1.0f);

        float Q01 = nWy * nWx, Q02 = nWz * nWx, Q12 = nWz * nWy;
        float Q00 = -(nWz * nWz + nWy * nWy);
        float Q11 = -(nWz * nWz + nWx * nWx);
        float Q22 = -(nWy * nWy + nWx * nWx);

        float A00 = 1.0f + Q00 * ca;
        float A01 = fmaf(-nWz, sa, Q01 * ca);
        float A02 = fmaf( nWy, sa, Q02 * ca);
        float A10 = fmaf( nWz, sa, Q01 * ca);
        float A11 = 1.0f + Q11 * ca;
        float A12 = fmaf(-nWx, sa, Q12 * ca);
        float A20 = fmaf(-nWy, sa, Q02 * ca);
        float A21 = fmaf( nWx, sa, Q12 * ca);
        float A22 = 1.0f + Q22 * ca;

        float nR00 = R00*A00 + R01*A10 + R02*A20;
        float nR01 = R00*A01 + R01*A11 + R02*A21;
        float nR02 = R00*A02 + R01*A12 + R02*A22;
        float nR10 = R10*A00 + R11*A10 + R12*A20;
        float nR11 = R10*A01 + R11*A11 + R12*A21;
        float nR12 = R10*A02 + R11*A12 + R12*A22;
        float nR20 = R20*A00 + R21*A10 + R22*A20;
        float nR21 = R20*A01 + R21*A11 + R22*A21;
        float nR22 = R20*A02 + R21*A12 + R22*A22;

        /* outputs */
        float* o = outb + (size_t)t * 162;

        /* body state: lane p stores value p via select tree (2 STG total) */
        {
            float s0_0 = b0 ? nXy  : nXx;
            float s0_1 = b0 ? nVx  : nXz;
            float s0_2 = b0 ? nVz  : nVy;
            float s0_3 = b0 ? nWy  : nWx;
            float s0_4 = b0 ? nR00 : nWz;
            float s0_5 = b0 ? nR02 : nR01;
            float s0_6 = b0 ? nR11 : nR10;
            float s0_7 = b0 ? nR20 : nR12;
            float s1_0 = b1 ? s0_1 : s0_0;
            float s1_1 = b1 ? s0_3 : s0_2;
            float s1_2 = b1 ? s0_5 : s0_4;
            float s1_3 = b1 ? s0_7 : s0_6;
            float s2_0 = b2 ? s1_1 : s1_0;
            float s2_1 = b2 ? s1_3 : s1_2;
            float val  = b3 ? s2_1 : s2_0;
            o[p] = val;
            float ext = b0 ? nR22 : nR21;
            if (p < 2) o[16 + p] = ext;
        }

        o[18  + 3 * p] = npx; o[19  + 3 * p] = npy; o[20  + 3 * p] = npz;
        o[66  + 3 * p] = Fsx; o[67  + 3 * p] = Fsy; o[68  + 3 * p] = Fsz;
        o[114 + 3 * p] = Ffx; o[115 + 3 * p] = Ffy; o[116 + 3 * p] = Ffz;

        /* commit */
        Xx = nXx; Xy = nXy; Xz = nXz;
        Vx = nVx; Vy = nVy; Vz = nVz;
        Wx = nWx; Wy = nWy; Wz = nWz;
        px = npx; py = npy; pz = npz;
        pvx = npvx; pvy = npvy; pvz = npvz;
        R00 = nR00; R01 = nR01; R02 = nR02;
        R10 = nR10; R11 = nR11; R12 = nR12;
        R20 = nR20; R21 = nR21; R22 = nR22;
    }
}

extern "C" void kernel_launch(void* const* d_in, const int* in_sizes, int n_in,
                              void* d_out, int out_size)
{
    const float* z_grid   = (const float*)d_in[0];
    const float* controls = (const float*)d_in[1];
    const float* rpts     = (const float*)d_in[2];
    const float* Iinv     = (const float*)d_in[3];
    float*       out      = (float*)d_out;

    int B = in_sizes[0] / GRIDN;
    int T = in_sizes[1] / (B * 2);

    int nblk = (B + 1) / 2;
    size_t smem_bytes = (size_t)(2 * GRIDN + 4 * T) * sizeof(float);
    cudaFuncSetAttribute(physics_kernel,
                         cudaFuncAttributeMaxDynamicSharedMemorySize,
                         (int)smem_bytes);

    physics_kernel<<<nblk, 128, smem_bytes>>>(z_grid, controls, rpts, Iinv, out, B, T);
}

// round 8
// speedup vs baseline: 3.8261x; 1.0320x over previous
#include <cuda_runtime.h>
#include <math.h>

#define HW      128
#define GRIDN   (HW*HW)

#define D_MAXF  6.4f
#define KSTIFF  5000.0f
#define KDAMP   894.4271909999159f
#define KFRIC   0.5f
#define MGRAV   392.40000000000003f
#define DTF     0.01f
#define DT2F    1e-4f
#define RK4C    0.01005016666708333f   /* collapsed RK4, dt=0.01 */

__device__ __forceinline__ float clampi(float v) {
    return fminf(fmaxf(v, 0.0f), 126.0f);
}

__device__ __forceinline__ float bilin(const float* __restrict__ g, float xi, float yi) {
    float x0f = floorf(xi), y0f = floorf(yi);
    int   x0  = (int)x0f,   y0  = (int)y0f;
    float wx  = xi - x0f,   wy  = yi - y0f;
    const float* r = g + (x0 * HW + y0);
    float a = r[0], b = r[1], c = r[HW], d = r[HW + 1];
    float z0 = fmaf(wx, c - a, a);
    float z1 = fmaf(wx, d - b, b);
    return fmaf(wy, z1 - z0, z0);
}

__device__ __forceinline__ float rsum16(float v) {
    v += __shfl_xor_sync(0xffffffffu, v, 1);
    v += __shfl_xor_sync(0xffffffffu, v, 2);
    v += __shfl_xor_sync(0xffffffffu, v, 4);
    v += __shfl_xor_sync(0xffffffffu, v, 8);
    return v;
}

__device__ __forceinline__ float ftanh(float x) {
    float xc = fminf(fmaxf(x, -15.0f), 15.0f);
    float e  = __expf(2.0f * xc);
    return 1.0f - __fdividef(2.0f, e + 1.0f);
}

/* Position/velocity-only spring pipeline stage: terrain -> normal ->
   contact -> spring force + friction magnitude. Depends exclusively on
   (p, pv), so it can run one step ahead of its consumers. */
__device__ __forceinline__ void spring_calc(
    const float* __restrict__ g,
    float px, float py, float pz,
    float pvx, float pvy, float pvz,
    float& Fsx, float& Fsy, float& Fsz, float& kN)
{
    float xi = fmaf(px, 10.0f, 64.0f);
    float yi = fmaf(py, 10.0f, 64.0f);
    float z, nx, ny;

    bool fastok = (xi >= 1.0f) && (xi <= 125.0f) &&
                  (yi >= 1.0f) && (yi <= 125.0f);
    if (__all_sync(0xffffffffu, fastok)) {
        float x0f = floorf(xi), y0f = floorf(yi);
        int   x0  = (int)x0f,   y0  = (int)y0f;
        float wx  = xi - x0f,   wy  = yi - y0f;
        const float* r = g + ((x0 - 1) * HW + y0);
        float A0 = r[0],      B0 = r[1];
        float A1 = r[HW],     B1 = r[HW + 1];
        float A2 = r[2 * HW], B2 = r[2 * HW + 1];
        float A3 = r[3 * HW], B3 = r[3 * HW + 1];
        float C0 = r[HW - 1],     C1 = r[2 * HW - 1];
        float D0 = r[HW + 2],     D1 = r[2 * HW + 2];

        float zx0 = fmaf(wx, A2 - A1, A1);
        float zx1 = fmaf(wx, B2 - B1, B1);
        z         = fmaf(wy, zx1 - zx0, zx0);
        float zp0 = fmaf(wx, A3 - A2, A2);
        float zp1 = fmaf(wx, B3 - B2, B2);
        float zxp = fmaf(wy, zp1 - zp0, zp0);
        float zm0 = fmaf(wx, A1 - A0, A0);
        float zm1 = fmaf(wx, B1 - B0, B0);
        float zxm = fmaf(wy, zm1 - zm0, zm0);
        float zd  = fmaf(wx, D1 - D0, D0);
        float zyp = fmaf(wy, zd - zx1, zx1);
        float zc  = fmaf(wx, C1 - C0, C0);
        float zym = fmaf(wy, zx0 - zc, zc);

        nx = (zxm - zxp) * 5.0f;
        ny = (zym - zyp) * 5.0f;
    } else {
        float xic = clampi(xi);
        float yic = clampi(yi);
        float xip = clampi(fmaf(px, 10.0f, 65.0f));
        float xim = clampi(fmaf(px, 10.0f, 63.0f));
        float yip = clampi(fmaf(py, 10.0f, 65.0f));
        float yim = clampi(fmaf(py, 10.0f, 63.0f));
        z         = bilin(g, xic, yic);
        float zxp = bilin(g, xip, yic);
        float zxm = bilin(g, xim, yic);
        float zyp = bilin(g, xic, yip);
        float zym = bilin(g, xic, yim);
        nx = (zxm - zxp) * 5.0f;
        ny = (zym - zyp) * 5.0f;
    }

    float dh = pz - z;
    bool  on = (px >= -D_MAXF) && (px <= D_MAXF) &&
               (py >= -D_MAXF) && (py <= D_MAXF);
    float contact = (dh <= 0.0f && on) ? 1.0f : 0.0f;

    float rnn = rsqrtf(fmaf(nx, nx, fmaf(ny, ny, 1.0f)));
    float nnx = nx * rnn, nny = ny * rnn, nnz = rnn;

    float xdn = pvx * nnx + pvy * nny + pvz * nnz;
    float fm  = -(KSTIFF * dh + KDAMP * xdn) * contact;
    Fsx = fm * nnx; Fsy = fm * nny; Fsz = fm * nnz;
    kN  = KFRIC * fabsf(fm);
}

__global__ void __launch_bounds__(128, 1)
physics_kernel(const float* __restrict__ z_grid,
               const float* __restrict__ controls,
               const float* __restrict__ rpts,
               const float* __restrict__ Iinv,
               float* __restrict__ out,
               int B, int T)
{
    extern __shared__ float smem[];
    float* sg = smem;
    float* sc = smem + 2 * GRIDN;

    const int blk = blockIdx.x;
    const int tid = threadIdx.x;
    const int bA  = 2 * blk;
    const int bB  = (2 * blk + 1 < B) ? (2 * blk + 1) : (B - 1);

    {
        const float4* srcA = reinterpret_cast<const float4*>(z_grid + (size_t)bA * GRIDN);
        const float4* srcB = reinterpret_cast<const float4*>(z_grid + (size_t)bB * GRIDN);
        float4* dstA = reinterpret_cast<float4*>(sg);
        float4* dstB = reinterpret_cast<float4*>(sg + GRIDN);
        #pragma unroll 4
        for (int i = tid; i < GRIDN / 4; i += 128) { dstA[i] = srcA[i]; dstB[i] = srcB[i]; }
        const float* csA = controls + (size_t)bA * T * 2;
        const float* csB = controls + (size_t)bB * T * 2;
        for (int i = tid; i < T * 2; i += 128) { sc[i] = csA[i]; sc[2 * T + i] = csB[i]; }
    }
    __syncthreads();
    if (tid >= 32) return;

    const int     lane = tid;
    const int     half = lane >> 4;
    const int     p    = lane & 15;
    const float*  g    = sg + half * GRIDN;
    const float2* cs2  = reinterpret_cast<const float2*>(sc + half * 2 * T);

    const bool b0 = (p & 1), b1 = (p & 2), b2 = (p & 4), b3 = (p & 8);

    float rpx = rpts[3 * p + 0], rpy = rpts[3 * p + 1], rpz = rpts[3 * p + 2];

    float my = rsum16(rpy) * (1.0f / 16.0f);
    const bool isL = rpy > my;
    const bool isR = rpy < my;

    const float I00 = Iinv[0], I01 = Iinv[1], I02 = Iinv[2];
    const float I10 = Iinv[3], I11 = Iinv[4], I12 = Iinv[5];
    const float I20 = Iinv[6], I21 = Iinv[7], I22 = Iinv[8];

    float Xx = 0.f, Xy = 0.f, Xz = 1.f;
    float Vx = 0.f, Vy = 0.f, Vz = 0.f;
    float Wx = 0.f, Wy = 0.f, Wz = 0.f;
    float R00 = 1.f, R01 = 0.f, R02 = 0.f;
    float R10 = 0.f, R11 = 1.f, R12 = 0.f;
    float R20 = 0.f, R21 = 0.f, R22 = 1.f;
    float px = rpx, py = rpy, pz = 1.0f + rpz;
    float pvx = 0.f, pvy = 0.f, pvz = 0.f;

    /* ---- pipeline prologue: spring state + thrust for step 0 ---- */
    float Fsx, Fsy, Fsz, kN;
    spring_calc(g, px, py, pz, pvx, pvy, pvz, Fsx, Fsy, Fsz, kN);
    float rtn0 = rsqrtf(R00 * R00 + R10 * R10 + R20 * R20);
    float tx = R00 * rtn0, ty = R10 * rtn0, tz = R20 * rtn0;

    float* outb = out + (size_t)(half ? bB : bA) * T * 162;

    #pragma unroll 2
    for (int t = 0; t < T; ++t) {
        float2 u = cs2[t];

        /* friction (thrust, kN, Fs, pv all carried -> starts immediately) */
        float us = isL ? u.x : u.y;
        bool  lr = isL || isR;
        float Ffx = lr ? kN * ftanh(us * tx - pvx) : 0.0f;
        float Ffy = lr ? kN * ftanh(us * ty - pvy) : 0.0f;
        float Ffz = lr ? kN * ftanh(us * tz - pvz) : 0.0f;

        float rx = px - Xx, ry = py - Xy, rz = pz - Xz;

        float Ftx = Fsx + Ffx, Fty = Fsy + Ffy, Ftz = Fsz + Ffz;
        float tqx = ry * Ftz - rz * Fty;
        float tqy = rz * Ftx - rx * Ftz;
        float tqz = rx * Fty - ry * Ftx;

        /* next point state: independent of forces, overlaps the butterflies */
        float npvx = Vx + (Wy * rz - Wz * ry);
        float npvy = Vy + (Wz * rx - Wx * rz);
        float npvz = Vz + (Wx * ry - Wy * rx);
        float npx = fmaf(npvx, RK4C, px);
        float npy = fmaf(npvy, RK4C, py);
        float npz = fmaf(npvz, RK4C, pz);

        float Tqx = rsum16(tqx), Tqy = rsum16(tqy), Tqz = rsum16(tqz);
        float SFx = rsum16(Ftx), SFy = rsum16(Fty), SFz = rsum16(Ftz);

        /* per-point stores sit in the SHFL latency shadow */
        float* o = outb + (size_t)t * 162;
        o[18  + 3 * p] = npx; o[19  + 3 * p] = npy; o[20  + 3 * p] = npz;
        o[66  + 3 * p] = Fsx; o[67  + 3 * p] = Fsy; o[68  + 3 * p] = Fsz;
        o[114 + 3 * p] = Ffx; o[115 + 3 * p] = Ffy; o[116 + 3 * p] = Ffz;

        float odx = Tqx * I00 + Tqy * I01 + Tqz * I02;
        float ody = Tqx * I10 + Tqy * I11 + Tqz * I12;
        float odz = Tqx * I20 + Tqy * I21 + Tqz * I22;

        float ax = SFx * (0.025f / 16.0f);
        float ay = SFy * (0.025f / 16.0f);
        float az = fmaf(SFz, 0.025f / 16.0f, -MGRAV * 0.025f);

        float nVx = fmaf(ax, RK4C, Vx), nVy = fmaf(ay, RK4C, Vy), nVz = fmaf(az, RK4C, Vz);
        float nXx = fmaf(nVx, RK4C, Xx), nXy = fmaf(nVy, RK4C, Xy), nXz = fmaf(nVz, RK4C, Xz);
        float nWx = fmaf(odx, RK4C, Wx), nWy = fmaf(ody, RK4C, Wy), nWz = fmaf(odz, RK4C, Wz);

        /* Rodrigues via even polynomials in q = |w|^2 dt^2 */
        float ws = nWx * nWx + nWy * nWy + nWz * nWz;
        float q  = ws * DT2F;
        float sa = DTF * fmaf(q, fmaf(q, fmaf(q, -1.0f/5040.0f, 1.0f/120.0f), -1.0f/6.0f), 1.0f);
        float ca = (0.5f * DT2F) *
                   fmaf(q, fmaf(q, fmaf(q, -1.0f/20160.0f, 1.0f/360.0f), -1.0f/12.0f), 1.0f);

        float Q01 = nWy * nWx, Q02 = nWz * nWx, Q12 = nWz * nWy;
        float Q00 = -(nWz * nWz + nWy * nWy);
        float Q11 = -(nWz * nWz + nWx * nWx);
        float Q22 = -(nWy * nWy + nWx * nWx);

        float A00 = 1.0f + Q00 * ca;
        float A01 = fmaf(-nWz, sa, Q01 * ca);
        float A02 = fmaf( nWy, sa, Q02 * ca);
        float A10 = fmaf( nWz, sa, Q01 * ca);
        float A11 = 1.0f + Q11 * ca;
        float A12 = fmaf(-nWx, sa, Q12 * ca);
        float A20 = fmaf(-nWy, sa, Q02 * ca);
        float A21 = fmaf( nWx, sa, Q12 * ca);
        float A22 = 1.0f + Q22 * ca;

        float nR00 = R00*A00 + R01*A10 + R02*A20;
        float nR01 = R00*A01 + R01*A11 + R02*A21;
        float nR02 = R00*A02 + R01*A12 + R02*A22;
        float nR10 = R10*A00 + R11*A10 + R12*A20;
        float nR11 = R10*A01 + R11*A11 + R12*A21;
        float nR12 = R10*A02 + R11*A12 + R12*A22;
        float nR20 = R20*A00 + R21*A10 + R22*A20;
        float nR21 = R20*A01 + R21*A11 + R22*A21;
        float nR22 = R20*A02 + R21*A12 + R22*A22;

        /* thrust for step t+1 — right after nR, off next step's spine */
        float rtn = rsqrtf(nR00 * nR00 + nR10 * nR10 + nR20 * nR20);
        tx = nR00 * rtn; ty = nR10 * rtn; tz = nR20 * rtn;

        /* body-state store: lane p stores value p via select tree */
        {
            float s0_0 = b0 ? nXy  : nXx;
            float s0_1 = b0 ? nVx  : nXz;
            float s0_2 = b0 ? nVz  : nVy;
            float s0_3 = b0 ? nWy  : nWx;
            float s0_4 = b0 ? nR00 : nWz;
            float s0_5 = b0 ? nR02 : nR01;
            float s0_6 = b0 ? nR11 : nR10;
            float s0_7 = b0 ? nR20 : nR12;
            float s1_0 = b1 ? s0_1 : s0_0;
            float s1_1 = b1 ? s0_3 : s0_2;
            float s1_2 = b1 ? s0_5 : s0_4;
            float s1_3 = b1 ? s0_7 : s0_6;
            float s2_0 = b2 ? s1_1 : s1_0;
            float s2_1 = b2 ? s1_3 : s1_2;
            float val  = b3 ? s2_1 : s2_0;
            o[p] = val;
            float ext = b0 ? nR22 : nR21;
            if (p < 2) o[16 + p] = ext;
        }

        /* spring pipeline stage for step t+1 (LDS/rsqrt hidden in tail) */
        spring_calc(g, npx, npy, npz, npvx, npvy, npvz, Fsx, Fsy, Fsz, kN);

        /* commit */
        Xx = nXx; Xy = nXy; Xz = nXz;
        Vx = nVx; Vy = nVy; Vz = nVz;
        Wx = nWx; Wy = nWy; Wz = nWz;
        px = npx; py = npy; pz = npz;
        pvx = npvx; pvy = npvy; pvz = npvz;
        R00 = nR00; R01 = nR01; R02 = nR02;
        R10 = nR10; R11 = nR11; R12 = nR12;
        R20 = nR20; R21 = nR21; R22 = nR22;
    }
}

extern "C" void kernel_launch(void* const* d_in, const int* in_sizes, int n_in,
                              void* d_out, int out_size)
{
    const float* z_grid   = (const float*)d_in[0];
    const float* controls = (const float*)d_in[1];
    const float* rpts     = (const float*)d_in[2];
    const float* Iinv     = (const float*)d_in[3];
    float*       out      = (float*)d_out;

    int B = in_sizes[0] / GRIDN;
    int T = in_sizes[1] / (B * 2);

    int nblk = (B + 1) / 2;
    size_t smem_bytes = (size_t)(2 * GRIDN + 4 * T) * sizeof(float);
    cudaFuncSetAttribute(physics_kernel,
                         cudaFuncAttributeMaxDynamicSharedMemorySize,
                         (int)smem_bytes);

    physics_kernel<<<nblk, 128, smem_bytes>>>(z_grid, controls, rpts, Iinv, out, B, T);
}

// round 9
// speedup vs baseline: 4.0791x; 1.0661x over previous
#include <cuda_runtime.h>
#include <math.h>

#define HW      128
#define GRIDN   (HW*HW)

#define D_MAXF  6.4f
#define KSTIFF  5000.0f
#define KDAMP   894.4271909999159f
#define KFRIC   0.5f
#define MGRAV   392.40000000000003f
#define DTF     0.01f
#define DT2F    1e-4f
#define RK4C    0.01005016666708333f   /* collapsed RK4, dt=0.01 */

__device__ __forceinline__ float clampi(float v) {
    return fminf(fmaxf(v, 0.0f), 126.0f);
}

__device__ __forceinline__ float bilin(const float* __restrict__ g, float xi, float yi) {
    float x0f = floorf(xi), y0f = floorf(yi);
    int   x0  = (int)x0f,   y0  = (int)y0f;
    float wx  = xi - x0f,   wy  = yi - y0f;
    const float* r = g + (x0 * HW + y0);
    float a = r[0], b = r[1], c = r[HW], d = r[HW + 1];
    float z0 = fmaf(wx, c - a, a);
    float z1 = fmaf(wx, d - b, b);
    return fmaf(wy, z1 - z0, z0);
}

__device__ __forceinline__ float rsum16(float v) {
    v += __shfl_xor_sync(0xffffffffu, v, 1);
    v += __shfl_xor_sync(0xffffffffu, v, 2);
    v += __shfl_xor_sync(0xffffffffu, v, 4);
    v += __shfl_xor_sync(0xffffffffu, v, 8);
    return v;
}

/* HW tanh (MUFU.TANH): single instruction, saturates correctly */
__device__ __forceinline__ float ftanh(float x) {
    float y;
    asm("tanh.approx.f32 %0, %1;" : "=f"(y) : "f"(x));
    return y;
}

/* Position/velocity-only pipeline stage: terrain -> normal -> contact ->
   spring force + friction magnitude. */
__device__ __forceinline__ void spring_calc(
    const float* __restrict__ g,
    float px, float py, float pz,
    float pvx, float pvy, float pvz,
    float& Fsx, float& Fsy, float& Fsz, float& kN)
{
    float xi = fmaf(px, 10.0f, 64.0f);
    float yi = fmaf(py, 10.0f, 64.0f);
    float z, nx, ny;

    bool fastok = (xi >= 1.0f) && (xi <= 125.0f) &&
                  (yi >= 1.0f) && (yi <= 125.0f);
    if (__all_sync(0xffffffffu, fastok)) {
        float x0f = floorf(xi), y0f = floorf(yi);
        int   x0  = (int)x0f,   y0  = (int)y0f;
        float wx  = xi - x0f,   wy  = yi - y0f;
        const float* r = g + ((x0 - 1) * HW + y0);
        float A0 = r[0],      B0 = r[1];
        float A1 = r[HW],     B1 = r[HW + 1];
        float A2 = r[2 * HW], B2 = r[2 * HW + 1];
        float A3 = r[3 * HW], B3 = r[3 * HW + 1];
        float C0 = r[HW - 1],     C1 = r[2 * HW - 1];
        float D0 = r[HW + 2],     D1 = r[2 * HW + 2];

        float zx0 = fmaf(wx, A2 - A1, A1);
        float zx1 = fmaf(wx, B2 - B1, B1);
        z         = fmaf(wy, zx1 - zx0, zx0);
        float zp0 = fmaf(wx, A3 - A2, A2);
        float zp1 = fmaf(wx, B3 - B2, B2);
        float zxp = fmaf(wy, zp1 - zp0, zp0);
        float zm0 = fmaf(wx, A1 - A0, A0);
        float zm1 = fmaf(wx, B1 - B0, B0);
        float zxm = fmaf(wy, zm1 - zm0, zm0);
        float zd  = fmaf(wx, D1 - D0, D0);
        float zyp = fmaf(wy, zd - zx1, zx1);
        float zc  = fmaf(wx, C1 - C0, C0);
        float zym = fmaf(wy, zx0 - zc, zc);

        nx = (zxm - zxp) * 5.0f;
        ny = (zym - zyp) * 5.0f;
    } else {
        float xic = clampi(xi);
        float yic = clampi(yi);
        float xip = clampi(fmaf(px, 10.0f, 65.0f));
        float xim = clampi(fmaf(px, 10.0f, 63.0f));
        float yip = clampi(fmaf(py, 10.0f, 65.0f));
        float yim = clampi(fmaf(py, 10.0f, 63.0f));
        z         = bilin(g, xic, yic);
        float zxp = bilin(g, xip, yic);
        float zxm = bilin(g, xim, yic);
        float zyp = bilin(g, xic, yip);
        float zym = bilin(g, xic, yim);
        nx = (zxm - zxp) * 5.0f;
        ny = (zym - zyp) * 5.0f;
    }

    float dh = pz - z;
    bool  on = (px >= -D_MAXF) && (px <= D_MAXF) &&
               (py >= -D_MAXF) && (py <= D_MAXF);
    float contact = (dh <= 0.0f && on) ? 1.0f : 0.0f;

    float rnn = rsqrtf(fmaf(nx, nx, fmaf(ny, ny, 1.0f)));
    float nnx = nx * rnn, nny = ny * rnn, nnz = rnn;

    float xdn = pvx * nnx + pvy * nny + pvz * nnz;
    float fm  = -(KSTIFF * dh + KDAMP * xdn) * contact;
    Fsx = fm * nnx; Fsy = fm * nny; Fsz = fm * nnz;
    kN  = KFRIC * fabsf(fm);
}

__global__ void __launch_bounds__(128, 1)
physics_kernel(const float* __restrict__ z_grid,
               const float* __restrict__ controls,
               const float* __restrict__ rpts,
               const float* __restrict__ Iinv,
               float* __restrict__ out,
               int B, int T)
{
    extern __shared__ float smem[];
    float* sg = smem;
    float* sc = smem + 2 * GRIDN;

    const int blk = blockIdx.x;
    const int tid = threadIdx.x;
    const int bA  = 2 * blk;
    const int bB  = (2 * blk + 1 < B) ? (2 * blk + 1) : (B - 1);

    {
        const float4* srcA = reinterpret_cast<const float4*>(z_grid + (size_t)bA * GRIDN);
        const float4* srcB = reinterpret_cast<const float4*>(z_grid + (size_t)bB * GRIDN);
        float4* dstA = reinterpret_cast<float4*>(sg);
        float4* dstB = reinterpret_cast<float4*>(sg + GRIDN);
        #pragma unroll 4
        for (int i = tid; i < GRIDN / 4; i += 128) { dstA[i] = srcA[i]; dstB[i] = srcB[i]; }
        const float* csA = controls + (size_t)bA * T * 2;
        const float* csB = controls + (size_t)bB * T * 2;
        for (int i = tid; i < T * 2; i += 128) { sc[i] = csA[i]; sc[2 * T + i] = csB[i]; }
    }
    __syncthreads();
    if (tid >= 32) return;

    const int     lane = tid;
    const int     half = lane >> 4;
    const int     p    = lane & 15;
    const float*  g    = sg + half * GRIDN;
    const float2* cs2  = reinterpret_cast<const float2*>(sc + half * 2 * T);

    const bool b0 = (p & 1), b1 = (p & 2), b2 = (p & 4), b3 = (p & 8);

    float rpx = rpts[3 * p + 0], rpy = rpts[3 * p + 1], rpz = rpts[3 * p + 2];

    float my = rsum16(rpy) * (1.0f / 16.0f);
    const bool isL = rpy > my;
    const bool isR = rpy < my;

    const float I00 = Iinv[0], I01 = Iinv[1], I02 = Iinv[2];
    const float I10 = Iinv[3], I11 = Iinv[4], I12 = Iinv[5];
    const float I20 = Iinv[6], I21 = Iinv[7], I22 = Iinv[8];

    float Xx = 0.f, Xy = 0.f, Xz = 1.f;
    float Vx = 0.f, Vy = 0.f, Vz = 0.f;
    float Wx = 0.f, Wy = 0.f, Wz = 0.f;
    float R00 = 1.f, R01 = 0.f, R02 = 0.f;
    float R10 = 0.f, R11 = 1.f, R12 = 0.f;
    float R20 = 0.f, R21 = 0.f, R22 = 1.f;
    float px = rpx, py = rpy, pz = 1.0f + rpz;
    float pvx = 0.f, pvy = 0.f, pvz = 0.f;

    /* pipeline prologue: spring state, thrust, first control */
    float Fsx, Fsy, Fsz, kN;
    spring_calc(g, px, py, pz, pvx, pvy, pvz, Fsx, Fsy, Fsz, kN);
    float rtn0 = rsqrtf(R00 * R00 + R10 * R10 + R20 * R20);
    float tx = R00 * rtn0, ty = R10 * rtn0, tz = R20 * rtn0;
    float2 u = cs2[0];

    float* outb = out + (size_t)(half ? bB : bA) * T * 162;

    #pragma unroll 4
    for (int t = 0; t < T; ++t) {
        /* friction: thrust, kN, Fs, pv, u all carried -> starts immediately */
        float us = isL ? u.x : u.y;
        bool  lr = isL || isR;
        float Ffx = lr ? kN * ftanh(us * tx - pvx) : 0.0f;
        float Ffy = lr ? kN * ftanh(us * ty - pvy) : 0.0f;
        float Ffz = lr ? kN * ftanh(us * tz - pvz) : 0.0f;

        float rx = px - Xx, ry = py - Xy, rz = pz - Xz;

        float Ftx = Fsx + Ffx, Fty = Fsy + Ffy, Ftz = Fsz + Ffz;
        float tqx = ry * Ftz - rz * Fty;
        float tqy = rz * Ftx - rx * Ftz;
        float tqz = rx * Fty - ry * Ftx;

        /* next point state: force-independent, overlaps the butterflies */
        float npvx = Vx + (Wy * rz - Wz * ry);
        float npvy = Vy + (Wz * rx - Wx * rz);
        float npvz = Vz + (Wx * ry - Wy * rx);
        float npx = fmaf(npvx, RK4C, px);
        float npy = fmaf(npvy, RK4C, py);
        float npz = fmaf(npvz, RK4C, pz);

        /* prefetch next control (off-chain) */
        int tn = (t + 1 < T) ? (t + 1) : t;
        float2 un = cs2[tn];

        float Tqx = rsum16(tqx), Tqy = rsum16(tqy), Tqz = rsum16(tqz);
        float SFx = rsum16(Ftx), SFy = rsum16(Fty), SFz = rsum16(Ftz);

        /* per-point stores in the SHFL latency shadow */
        float* o = outb + (size_t)t * 162;
        o[18  + 3 * p] = npx; o[19  + 3 * p] = npy; o[20  + 3 * p] = npz;
        o[66  + 3 * p] = Fsx; o[67  + 3 * p] = Fsy; o[68  + 3 * p] = Fsz;
        o[114 + 3 * p] = Ffx; o[115 + 3 * p] = Ffy; o[116 + 3 * p] = Ffz;

        float odx = Tqx * I00 + Tqy * I01 + Tqz * I02;
        float ody = Tqx * I10 + Tqy * I11 + Tqz * I12;
        float odz = Tqx * I20 + Tqy * I21 + Tqz * I22;

        float ax = SFx * (0.025f / 16.0f);
        float ay = SFy * (0.025f / 16.0f);
        float az = fmaf(SFz, 0.025f / 16.0f, -MGRAV * 0.025f);

        float nVx = fmaf(ax, RK4C, Vx), nVy = fmaf(ay, RK4C, Vy), nVz = fmaf(az, RK4C, Vz);
        float nXx = fmaf(nVx, RK4C, Xx), nXy = fmaf(nVy, RK4C, Xy), nXz = fmaf(nVz, RK4C, Xz);
        float nWx = fmaf(odx, RK4C, Wx), nWy = fmaf(ody, RK4C, Wy), nWz = fmaf(odz, RK4C, Wz);

        /* Rodrigues via even polynomials in q = |w|^2 dt^2 */
        float ws = nWx * nWx + nWy * nWy + nWz * nWz;
        float q  = ws * DT2F;
        float sa = DTF * fmaf(q, fmaf(q, fmaf(q, -1.0f/5040.0f, 1.0f/120.0f), -1.0f/6.0f), 1.0f);
        float ca = (0.5f * DT2F) *
                   fmaf(q, fmaf(q, fmaf(q, -1.0f/20160.0f, 1.0f/360.0f), -1.0f/12.0f), 1.0f);

        float Q01 = nWy * nWx, Q02 = nWz * nWx, Q12 = nWz * nWy;
        float Q00 = -(nWz * nWz + nWy * nWy);
        float Q11 = -(nWz * nWz + nWx * nWx);
        float Q22 = -(nWy * nWy + nWx * nWx);

        float A00 = 1.0f + Q00 * ca;
        float A01 = fmaf(-nWz, sa, Q01 * ca);
        float A02 = fmaf( nWy, sa, Q02 * ca);
        float A10 = fmaf( nWz, sa, Q01 * ca);
        float A11 = 1.0f + Q11 * ca;
        float A12 = fmaf(-nWx, sa, Q12 * ca);
        float A20 = fmaf(-nWy, sa, Q02 * ca);
        float A21 = fmaf( nWx, sa, Q12 * ca);
        float A22 = 1.0f + Q22 * ca;

        float nR00 = R00*A00 + R01*A10 + R02*A20;
        float nR01 = R00*A01 + R01*A11 + R02*A21;
        float nR02 = R00*A02 + R01*A12 + R02*A22;
        float nR10 = R10*A00 + R11*A10 + R12*A20;
        float nR11 = R10*A01 + R11*A11 + R12*A21;
        float nR12 = R10*A02 + R11*A12 + R12*A22;
        float nR20 = R20*A00 + R21*A10 + R22*A20;
        float nR21 = R20*A01 + R21*A11 + R22*A21;
        float nR22 = R20*A02 + R21*A12 + R22*A22;

        /* thrust for step t+1 right after nR */
        float rtn = rsqrtf(nR00 * nR00 + nR10 * nR10 + nR20 * nR20);
        tx = nR00 * rtn; ty = nR10 * rtn; tz = nR20 * rtn;

        /* body-state store: lane p stores value p via select tree */
        {
            float s0_0 = b0 ? nXy  : nXx;
            float s0_1 = b0 ? nVx  : nXz;
            float s0_2 = b0 ? nVz  : nVy;
            float s0_3 = b0 ? nWy  : nWx;
            float s0_4 = b0 ? nR00 : nWz;
            float s0_5 = b0 ? nR02 : nR01;
            float s0_6 = b0 ? nR11 : nR10;
            float s0_7 = b0 ? nR20 : nR12;
            float s1_0 = b1 ? s0_1 : s0_0;
            float s1_1 = b1 ? s0_3 : s0_2;
            float s1_2 = b1 ? s0_5 : s0_4;
            float s1_3 = b1 ? s0_7 : s0_6;
            float s2_0 = b2 ? s1_1 : s1_0;
            float s2_1 = b2 ? s1_3 : s1_2;
            float val  = b3 ? s2_1 : s2_0;
            o[p] = val;
            float ext = b0 ? nR22 : nR21;
            if (p < 2) o[16 + p] = ext;
        }

        /* spring stage for t+1 */
        spring_calc(g, npx, npy, npz, npvx, npvy, npvz, Fsx, Fsy, Fsz, kN);

        /* commit */
        u = un;
        Xx = nXx; Xy = nXy; Xz = nXz;
        Vx = nVx; Vy = nVy; Vz = nVz;
        Wx = nWx; Wy = nWy; Wz = nWz;
        px = npx; py = npy; pz = npz;
        pvx = npvx; pvy = npvy; pvz = npvz;
        R00 = nR00; R01 = nR01; R02 = nR02;
        R10 = nR10; R11 = nR11; R12 = nR12;
        R20 = nR20; R21 = nR21; R22 = nR22;
    }
}

extern "C" void kernel_launch(void* const* d_in, const int* in_sizes, int n_in,
                              void* d_out, int out_size)
{
    const float* z_grid   = (const float*)d_in[0];
    const float* controls = (const float*)d_in[1];
    const float* rpts     = (const float*)d_in[2];
    const float* Iinv     = (const float*)d_in[3];
    float*       out      = (float*)d_out;

    int B = in_sizes[0] / GRIDN;
    int T = in_sizes[1] / (B * 2);

    int nblk = (B + 1) / 2;
    size_t smem_bytes = (size_t)(2 * GRIDN + 4 * T) * sizeof(float);
    cudaFuncSetAttribute(physics_kernel,
                         cudaFuncAttributeMaxDynamicSharedMemorySize,
                         (int)smem_bytes);

    physics_kernel<<<nblk, 128, smem_bytes>>>(z_grid, controls, rpts, Iinv, out, B, T);
}

// round 10
// speedup vs baseline: 4.4214x; 1.0839x over previous
#include <cuda_runtime.h>
#include <math.h>

#define HW      128
#define GRIDN   (HW*HW)

#define D_MAXF  6.4f
#define KSTIFF  5000.0f
#define KDAMP   894.4271909999159f
#define KFRIC   0.5f
#define MGRAV   392.40000000000003f
#define DTF     0.01f
#define DT2F    1e-4f
#define RK4C    0.01005016666708333f   /* collapsed RK4, dt=0.01 */

__device__ __forceinline__ float clampi(float v) {
    return fminf(fmaxf(v, 0.0f), 126.0f);
}

__device__ __forceinline__ float bilin(const float* __restrict__ g, float xi, float yi) {
    float x0f = floorf(xi), y0f = floorf(yi);
    int   x0  = (int)x0f,   y0  = (int)y0f;
    float wx  = xi - x0f,   wy  = yi - y0f;
    const float* r = g + (x0 * HW + y0);
    float a = r[0], b = r[1], c = r[HW], d = r[HW + 1];
    float z0 = fmaf(wx, c - a, a);
    float z1 = fmaf(wx, d - b, b);
    return fmaf(wy, z1 - z0, z0);
}

__device__ __forceinline__ float rsum16(float v) {
    v += __shfl_xor_sync(0xffffffffu, v, 1);
    v += __shfl_xor_sync(0xffffffffu, v, 2);
    v += __shfl_xor_sync(0xffffffffu, v, 4);
    v += __shfl_xor_sync(0xffffffffu, v, 8);
    return v;
}

__device__ __forceinline__ float ftanh(float x) {
    float y;
    asm("tanh.approx.f32 %0, %1;" : "=f"(y) : "f"(x));
    return y;
}

/* Position/velocity-only stage: terrain -> normal -> contact -> spring. */
__device__ __forceinline__ void spring_calc(
    const float* __restrict__ g,
    float px, float py, float pz,
    float pvx, float pvy, float pvz,
    float& Fsx, float& Fsy, float& Fsz, float& kN)
{
    float xi = fmaf(px, 10.0f, 64.0f);
    float yi = fmaf(py, 10.0f, 64.0f);
    float z, nx, ny;

    bool fastok = (xi >= 1.0f) && (xi <= 125.0f) &&
                  (yi >= 1.0f) && (yi <= 125.0f);
    if (__all_sync(0xffffffffu, fastok)) {
        float x0f = floorf(xi), y0f = floorf(yi);
        int   x0  = (int)x0f,   y0  = (int)y0f;
        float wx  = xi - x0f,   wy  = yi - y0f;
        const float* r = g + ((x0 - 1) * HW + y0);
        float A0 = r[0],      B0 = r[1];
        float A1 = r[HW],     B1 = r[HW + 1];
        float A2 = r[2 * HW], B2 = r[2 * HW + 1];
        float A3 = r[3 * HW], B3 = r[3 * HW + 1];
        float C0 = r[HW - 1],     C1 = r[2 * HW - 1];
        float D0 = r[HW + 2],     D1 = r[2 * HW + 2];

        float zx0 = fmaf(wx, A2 - A1, A1);
        float zx1 = fmaf(wx, B2 - B1, B1);
        z         = fmaf(wy, zx1 - zx0, zx0);
        float zp0 = fmaf(wx, A3 - A2, A2);
        float zp1 = fmaf(wx, B3 - B2, B2);
        float zxp = fmaf(wy, zp1 - zp0, zp0);
        float zm0 = fmaf(wx, A1 - A0, A0);
        float zm1 = fmaf(wx, B1 - B0, B0);
        float zxm = fmaf(wy, zm1 - zm0, zm0);
        float zd  = fmaf(wx, D1 - D0, D0);
        float zyp = fmaf(wy, zd - zx1, zx1);
        float zc  = fmaf(wx, C1 - C0, C0);
        float zym = fmaf(wy, zx0 - zc, zc);

        nx = (zxm - zxp) * 5.0f;
        ny = (zym - zyp) * 5.0f;
    } else {
        float xic = clampi(xi);
        float yic = clampi(yi);
        float xip = clampi(fmaf(px, 10.0f, 65.0f));
        float xim = clampi(fmaf(px, 10.0f, 63.0f));
        float yip = clampi(fmaf(py, 10.0f, 65.0f));
        float yim = clampi(fmaf(py, 10.0f, 63.0f));
        z         = bilin(g, xic, yic);
        float zxp = bilin(g, xip, yic);
        float zxm = bilin(g, xim, yic);
        float zyp = bilin(g, xic, yip);
        float zym = bilin(g, xic, yim);
        nx = (zxm - zxp) * 5.0f;
        ny = (zym - zyp) * 5.0f;
    }

    float dh = pz - z;
    bool  on = (px >= -D_MAXF) && (px <= D_MAXF) &&
               (py >= -D_MAXF) && (py <= D_MAXF);
    float contact = (dh <= 0.0f && on) ? 1.0f : 0.0f;

    float rnn = rsqrtf(fmaf(nx, nx, fmaf(ny, ny, 1.0f)));
    float nnx = nx * rnn, nny = ny * rnn, nnz = rnn;

    float xdn = pvx * nnx + pvy * nny + pvz * nnz;
    float fm  = -(KSTIFF * dh + KDAMP * xdn) * contact;
    Fsx = fm * nnx; Fsy = fm * nny; Fsz = fm * nnz;
    kN  = KFRIC * fabsf(fm);
}

__global__ void __launch_bounds__(128, 1)
physics_kernel(const float* __restrict__ z_grid,
               const float* __restrict__ controls,
               const float* __restrict__ rpts,
               const float* __restrict__ Iinv,
               float* __restrict__ out,
               int B, int T)
{
    extern __shared__ float smem[];
    float* sg = smem;
    float* sc = smem + 2 * GRIDN;

    const int blk = blockIdx.x;
    const int tid = threadIdx.x;
    const int bA  = 2 * blk;
    const int bB  = (2 * blk + 1 < B) ? (2 * blk + 1) : (B - 1);

    {
        const float4* srcA = reinterpret_cast<const float4*>(z_grid + (size_t)bA * GRIDN);
        const float4* srcB = reinterpret_cast<const float4*>(z_grid + (size_t)bB * GRIDN);
        float4* dstA = reinterpret_cast<float4*>(sg);
        float4* dstB = reinterpret_cast<float4*>(sg + GRIDN);
        #pragma unroll 4
        for (int i = tid; i < GRIDN / 4; i += 128) { dstA[i] = srcA[i]; dstB[i] = srcB[i]; }
        const float* csA = controls + (size_t)bA * T * 2;
        const float* csB = controls + (size_t)bB * T * 2;
        for (int i = tid; i < T * 2; i += 128) { sc[i] = csA[i]; sc[2 * T + i] = csB[i]; }
    }
    __syncthreads();
    if (tid >= 32) return;

    const int     lane = tid;
    const int     half = lane >> 4;
    const int     p    = lane & 15;
    const float*  g    = sg + half * GRIDN;
    const float2* cs2  = reinterpret_cast<const float2*>(sc + half * 2 * T);

    const bool b0 = (p & 1), b1 = (p & 2), b2 = (p & 4), b3 = (p & 8);

    float rpx = rpts[3 * p + 0], rpy = rpts[3 * p + 1], rpz = rpts[3 * p + 2];

    float my = rsum16(rpy) * (1.0f / 16.0f);
    const bool isL = rpy > my;
    const bool isR = rpy < my;

    const float I00 = Iinv[0], I01 = Iinv[1], I02 = Iinv[2];
    const float I10 = Iinv[3], I11 = Iinv[4], I12 = Iinv[5];
    const float I20 = Iinv[6], I21 = Iinv[7], I22 = Iinv[8];

    float Xx = 0.f, Xy = 0.f, Xz = 1.f;
    float Vx = 0.f, Vy = 0.f, Vz = 0.f;
    float Wx = 0.f, Wy = 0.f, Wz = 0.f;
    float R00 = 1.f, R01 = 0.f, R02 = 0.f;
    float R10 = 0.f, R11 = 1.f, R12 = 0.f;
    float R20 = 0.f, R21 = 0.f, R22 = 1.f;
    float px = rpx, py = rpy, pz = 1.0f + rpz;
    float pvx = 0.f, pvy = 0.f, pvz = 0.f;

    /* ---- prologue: spring, thrust, control, friction for step 0 ---- */
    float Fsx, Fsy, Fsz, kN;
    spring_calc(g, px, py, pz, pvx, pvy, pvz, Fsx, Fsy, Fsz, kN);
    float rtn0 = rsqrtf(R00 * R00 + R10 * R10 + R20 * R20);
    float tx = R00 * rtn0, ty = R10 * rtn0, tz = R20 * rtn0;
    float2 u = cs2[0];
    float us = isL ? u.x : u.y;
    const bool lr = isL || isR;
    float Ffx = lr ? kN * ftanh(us * tx - pvx) : 0.0f;
    float Ffy = lr ? kN * ftanh(us * ty - pvy) : 0.0f;
    float Ffz = lr ? kN * ftanh(us * tz - pvz) : 0.0f;

    float* outb = out + (size_t)(half ? bB : bA) * T * 162;

    #pragma unroll 4
    for (int t = 0; t < T; ++t) {
        /* head starts directly at total force (Ff carried from tail) */
        float rx = px - Xx, ry = py - Xy, rz = pz - Xz;

        float Ftx = Fsx + Ffx, Fty = Fsy + Ffy, Ftz = Fsz + Ffz;
        float tqx = ry * Ftz - rz * Fty;
        float tqy = rz * Ftx - rx * Ftz;
        float tqz = rx * Fty - ry * Ftx;

        /* next point state: force-independent, overlaps the butterflies */
        float npvx = Vx + (Wy * rz - Wz * ry);
        float npvy = Vy + (Wz * rx - Wx * rz);
        float npvz = Vz + (Wx * ry - Wy * rx);
        float npx = fmaf(npvx, RK4C, px);
        float npy = fmaf(npvy, RK4C, py);
        float npz = fmaf(npvz, RK4C, pz);

        /* prefetch next control (off-chain) */
        int tn = (t + 1 < T) ? (t + 1) : t;
        float2 un = cs2[tn];

        float Tqx = rsum16(tqx), Tqy = rsum16(tqy), Tqz = rsum16(tqz);
        float SFx = rsum16(Ftx), SFy = rsum16(Fty), SFz = rsum16(Ftz);

        /* per-point stores in the SHFL latency shadow */
        float* o = outb + (size_t)t * 162;
        o[18  + 3 * p] = npx; o[19  + 3 * p] = npy; o[20  + 3 * p] = npz;
        o[66  + 3 * p] = Fsx; o[67  + 3 * p] = Fsy; o[68  + 3 * p] = Fsz;
        o[114 + 3 * p] = Ffx; o[115 + 3 * p] = Ffy; o[116 + 3 * p] = Ffz;

        float odx = Tqx * I00 + Tqy * I01 + Tqz * I02;
        float ody = Tqx * I10 + Tqy * I11 + Tqz * I12;
        float odz = Tqx * I20 + Tqy * I21 + Tqz * I22;

        float ax = SFx * (0.025f / 16.0f);
        float ay = SFy * (0.025f / 16.0f);
        float az = fmaf(SFz, 0.025f / 16.0f, -MGRAV * 0.025f);

        float nVx = fmaf(ax, RK4C, Vx), nVy = fmaf(ay, RK4C, Vy), nVz = fmaf(az, RK4C, Vz);
        float nXx = fmaf(nVx, RK4C, Xx), nXy = fmaf(nVy, RK4C, Xy), nXz = fmaf(nVz, RK4C, Xz);
        float nWx = fmaf(odx, RK4C, Wx), nWy = fmaf(ody, RK4C, Wy), nWz = fmaf(odz, RK4C, Wz);

        /* Rodrigues, 3-term even polynomials in q = |w|^2 dt^2 */
        float ws = nWx * nWx + nWy * nWy + nWz * nWz;
        float q  = ws * DT2F;
        float sa = DTF * fmaf(q, fmaf(q, 1.0f/120.0f, -1.0f/6.0f), 1.0f);
        float ca = (0.5f * DT2F) * fmaf(q, fmaf(q, 1.0f/360.0f, -1.0f/12.0f), 1.0f);

        float Q01 = nWy * nWx, Q02 = nWz * nWx, Q12 = nWz * nWy;
        float Q00 = -(nWz * nWz + nWy * nWy);
        float Q11 = -(nWz * nWz + nWx * nWx);
        float Q22 = -(nWy * nWy + nWx * nWx);

        float A00 = 1.0f + Q00 * ca;
        float A01 = fmaf(-nWz, sa, Q01 * ca);
        float A02 = fmaf( nWy, sa, Q02 * ca);
        float A10 = fmaf( nWz, sa, Q01 * ca);
        float A11 = 1.0f + Q11 * ca;
        float A12 = fmaf(-nWx, sa, Q12 * ca);
        float A20 = fmaf(-nWy, sa, Q02 * ca);
        float A21 = fmaf( nWx, sa, Q12 * ca);
        float A22 = 1.0f + Q22 * ca;

        float nR00 = R00*A00 + R01*A10 + R02*A20;
        float nR01 = R00*A01 + R01*A11 + R02*A21;
        float nR02 = R00*A02 + R01*A12 + R02*A22;
        float nR10 = R10*A00 + R11*A10 + R12*A20;
        float nR11 = R10*A01 + R11*A11 + R12*A21;
        float nR12 = R10*A02 + R11*A12 + R12*A22;
        float nR20 = R20*A00 + R21*A10 + R22*A20;
        float nR21 = R20*A01 + R21*A11 + R22*A21;
        float nR22 = R20*A02 + R21*A12 + R22*A22;

        /* thrust via 1st-order rsqrt around 1 (R is orthonormal to ~5e-5):
           rsqrt(x) = 1.5 - 0.5x + O((x-1)^2) */
        float ws2 = nR00 * nR00 + nR10 * nR10 + nR20 * nR20;
        float rtn = fmaf(-0.5f, ws2, 1.5f);
        tx = nR00 * rtn; ty = nR10 * rtn; tz = nR20 * rtn;

        /* body-state store: lane p stores value p via select tree */
        {
            float s0_0 = b0 ? nXy  : nXx;
            float s0_1 = b0 ? nVx  : nXz;
            float s0_2 = b0 ? nVz  : nVy;
            float s0_3 = b0 ? nWy  : nWx;
            float s0_4 = b0 ? nR00 : nWz;
            float s0_5 = b0 ? nR02 : nR01;
            float s0_6 = b0 ? nR11 : nR10;
            float s0_7 = b0 ? nR20 : nR12;
            float s1_0 = b1 ? s0_1 : s0_0;
            float s1_1 = b1 ? s0_3 : s0_2;
            float s1_2 = b1 ? s0_5 : s0_4;
            float s1_3 = b1 ? s0_7 : s0_6;
            float s2_0 = b2 ? s1_1 : s1_0;
            float s2_1 = b2 ? s1_3 : s1_2;
            float val  = b3 ? s2_1 : s2_0;
            o[p] = val;
            float ext = b0 ? nR22 : nR21;
            if (p < 2) o[16 + p] = ext;
        }

        /* spring stage for t+1 */
        spring_calc(g, npx, npy, npz, npvx, npvy, npvz, Fsx, Fsy, Fsz, kN);

        /* friction for t+1 (thrust, kN, npv, un all ready) */
        float usn = isL ? un.x : un.y;
        Ffx = lr ? kN * ftanh(usn * tx - npvx) : 0.0f;
        Ffy = lr ? kN * ftanh(usn * ty - npvy) : 0.0f;
        Ffz = lr ? kN * ftanh(usn * tz - npvz) : 0.0f;

        /* commit */
        u = un;
        Xx = nXx; Xy = nXy; Xz = nXz;
        Vx = nVx; Vy = nVy; Vz = nVz;
        Wx = nWx; Wy = nWy; Wz = nWz;
        px = npx; py = npy; pz = npz;
        pvx = npvx; pvy = npvy; pvz = npvz;
        R00 = nR00; R01 = nR01; R02 = nR02;
        R10 = nR10; R11 = nR11; R12 = nR12;
        R20 = nR20; R21 = nR21; R22 = nR22;
    }
}

extern "C" void kernel_launch(void* const* d_in, const int* in_sizes, int n_in,
                              void* d_out, int out_size)
{
    const float* z_grid   = (const float*)d_in[0];
    const float* controls = (const float*)d_in[1];
    const float* rpts     = (const float*)d_in[2];
    const float* Iinv     = (const float*)d_in[3];
    float*       out      = (float*)d_out;

    int B = in_sizes[0] / GRIDN;
    int T = in_sizes[1] / (B * 2);

    int nblk = (B + 1) / 2;
    size_t smem_bytes = (size_t)(2 * GRIDN + 4 * T) * sizeof(float);
    cudaFuncSetAttribute(physics_kernel,
                         cudaFuncAttributeMaxDynamicSharedMemorySize,
                         (int)smem_bytes);

    physics_kernel<<<nblk, 128, smem_bytes>>>(z_grid, controls, rpts, Iinv, out, B, T);
}

// round 11
// speedup vs baseline: 4.5191x; 1.0221x over previous
#include <cuda_runtime.h>
#include <math.h>

#define HW      128
#define GRIDN   (HW*HW)

#define D_MAXF  6.4f
#define KSTIFF  5000.0f
#define KDAMP   894.4271909999159f
#define KFRIC   0.5f
#define MGRAV   392.40000000000003f
#define DTF     0.01f
#define DT2F    1e-4f
#define RK4C    0.01005016666708333f   /* collapsed RK4, dt=0.01 */
#define AMUL    (0.025f / 16.0f)       /* (1/16 mean) * (1/40 mass) */

__device__ __forceinline__ float clampi(float v) {
    return fminf(fmaxf(v, 0.0f), 126.0f);
}

__device__ __forceinline__ float bilin(const float* __restrict__ g, float xi, float yi) {
    float x0f = floorf(xi), y0f = floorf(yi);
    int   x0  = (int)x0f,   y0  = (int)y0f;
    float wx  = xi - x0f,   wy  = yi - y0f;
    const float* r = g + (x0 * HW + y0);
    float a = r[0], b = r[1], c = r[HW], d = r[HW + 1];
    float z0 = fmaf(wx, c - a, a);
    float z1 = fmaf(wx, d - b, b);
    return fmaf(wy, z1 - z0, z0);
}

__device__ __forceinline__ float rsum16(float v) {
    v += __shfl_xor_sync(0xffffffffu, v, 1);
    v += __shfl_xor_sync(0xffffffffu, v, 2);
    v += __shfl_xor_sync(0xffffffffu, v, 4);
    v += __shfl_xor_sync(0xffffffffu, v, 8);
    return v;
}

__device__ __forceinline__ float ftanh(float x) {
    float y;
    asm("tanh.approx.f32 %0, %1;" : "=f"(y) : "f"(x));
    return y;
}

/* Position/velocity-only stage: terrain -> normal -> contact -> spring. */
__device__ __forceinline__ void spring_calc(
    const float* __restrict__ g,
    float px, float py, float pz,
    float pvx, float pvy, float pvz,
    float& Fsx, float& Fsy, float& Fsz, float& kN)
{
    float xi = fmaf(px, 10.0f, 64.0f);
    float yi = fmaf(py, 10.0f, 64.0f);
    float z, nx, ny;

    bool fastok = (xi >= 1.0f) && (xi <= 125.0f) &&
                  (yi >= 1.0f) && (yi <= 125.0f);
    if (__all_sync(0xffffffffu, fastok)) {
        float x0f = floorf(xi), y0f = floorf(yi);
        int   x0  = (int)x0f,   y0  = (int)y0f;
        float wx  = xi - x0f,   wy  = yi - y0f;
        const float* r = g + ((x0 - 1) * HW + y0);
        float A0 = r[0],      B0 = r[1];
        float A1 = r[HW],     B1 = r[HW + 1];
        float A2 = r[2 * HW], B2 = r[2 * HW + 1];
        float A3 = r[3 * HW], B3 = r[3 * HW + 1];
        float C0 = r[HW - 1],     C1 = r[2 * HW - 1];
        float D0 = r[HW + 2],     D1 = r[2 * HW + 2];

        float zx0 = fmaf(wx, A2 - A1, A1);
        float zx1 = fmaf(wx, B2 - B1, B1);
        z         = fmaf(wy, zx1 - zx0, zx0);
        float zp0 = fmaf(wx, A3 - A2, A2);
        float zp1 = fmaf(wx, B3 - B2, B2);
        float zxp = fmaf(wy, zp1 - zp0, zp0);
        float zm0 = fmaf(wx, A1 - A0, A0);
        float zm1 = fmaf(wx, B1 - B0, B0);
        float zxm = fmaf(wy, zm1 - zm0, zm0);
        float zd  = fmaf(wx, D1 - D0, D0);
        float zyp = fmaf(wy, zd - zx1, zx1);
        float zc  = fmaf(wx, C1 - C0, C0);
        float zym = fmaf(wy, zx0 - zc, zc);

        nx = (zxm - zxp) * 5.0f;
        ny = (zym - zyp) * 5.0f;
    } else {
        float xic = clampi(xi);
        float yic = clampi(yi);
        float xip = clampi(fmaf(px, 10.0f, 65.0f));
        float xim = clampi(fmaf(px, 10.0f, 63.0f));
        float yip = clampi(fmaf(py, 10.0f, 65.0f));
        float yim = clampi(fmaf(py, 10.0f, 63.0f));
        z         = bilin(g, xic, yic);
        float zxp = bilin(g, xip, yic);
        float zxm = bilin(g, xim, yic);
        float zyp = bilin(g, xic, yip);
        float zym = bilin(g, xic, yim);
        nx = (zxm - zxp) * 5.0f;
        ny = (zym - zyp) * 5.0f;
    }

    float dh = pz - z;
    bool  on = (px >= -D_MAXF) && (px <= D_MAXF) &&
               (py >= -D_MAXF) && (py <= D_MAXF);
    float contact = (dh <= 0.0f && on) ? 1.0f : 0.0f;

    float rnn = rsqrtf(fmaf(nx, nx, fmaf(ny, ny, 1.0f)));
    float nnx = nx * rnn, nny = ny * rnn, nnz = rnn;

    float xdn = pvx * nnx + pvy * nny + pvz * nnz;
    float fm  = -(KSTIFF * dh + KDAMP * xdn) * contact;
    Fsx = fm * nnx; Fsy = fm * nny; Fsz = fm * nnz;
    kN  = KFRIC * fabsf(fm);
}

__global__ void __launch_bounds__(128, 1)
physics_kernel(const float* __restrict__ z_grid,
               const float* __restrict__ controls,
               const float* __restrict__ rpts,
               const float* __restrict__ Iinv,
               float* __restrict__ out,
               int B, int T)
{
    extern __shared__ float smem[];
    float* sg = smem;
    float* sc = smem + 2 * GRIDN;

    const int blk = blockIdx.x;
    const int tid = threadIdx.x;
    const int bA  = 2 * blk;
    const int bB  = (2 * blk + 1 < B) ? (2 * blk + 1) : (B - 1);

    {
        const float4* srcA = reinterpret_cast<const float4*>(z_grid + (size_t)bA * GRIDN);
        const float4* srcB = reinterpret_cast<const float4*>(z_grid + (size_t)bB * GRIDN);
        float4* dstA = reinterpret_cast<float4*>(sg);
        float4* dstB = reinterpret_cast<float4*>(sg + GRIDN);
        #pragma unroll 4
        for (int i = tid; i < GRIDN / 4; i += 128) { dstA[i] = srcA[i]; dstB[i] = srcB[i]; }
        const float* csA = controls + (size_t)bA * T * 2;
        const float* csB = controls + (size_t)bB * T * 2;
        for (int i = tid; i < T * 2; i += 128) { sc[i] = csA[i]; sc[2 * T + i] = csB[i]; }
    }
    __syncthreads();
    if (tid >= 32) return;

    const int     lane = tid;
    const int     half = lane >> 4;
    const int     p    = lane & 15;
    const float*  g    = sg + half * GRIDN;
    const float2* cs2  = reinterpret_cast<const float2*>(sc + half * 2 * T);

    const bool b0 = (p & 1), b1 = (p & 2), b2 = (p & 4), b3 = (p & 8);

    float rpx = rpts[3 * p + 0], rpy = rpts[3 * p + 1], rpz = rpts[3 * p + 2];

    float my = rsum16(rpy) * (1.0f / 16.0f);
    const bool isL = rpy > my;
    const bool isR = rpy < my;

    const float I00 = Iinv[0], I01 = Iinv[1], I02 = Iinv[2];
    const float I10 = Iinv[3], I11 = Iinv[4], I12 = Iinv[5];
    const float I20 = Iinv[6], I21 = Iinv[7], I22 = Iinv[8];

    float Xx = 0.f, Xy = 0.f, Xz = 1.f;
    float Vx = 0.f, Vy = 0.f, Vz = 0.f;
    float Wx = 0.f, Wy = 0.f, Wz = 0.f;
    float R00 = 1.f, R01 = 0.f, R02 = 0.f;
    float R10 = 0.f, R11 = 1.f, R12 = 0.f;
    float R20 = 0.f, R21 = 0.f, R22 = 1.f;
    float px = rpx, py = rpy, pz = 1.0f + rpz;
    float pvx = 0.f, pvy = 0.f, pvz = 0.f;

    /* ---- prologue: spring, thrust, control, friction for step 0 ---- */
    float Fsx, Fsy, Fsz, kN;
    spring_calc(g, px, py, pz, pvx, pvy, pvz, Fsx, Fsy, Fsz, kN);
    float rtn0 = rsqrtf(R00 * R00 + R10 * R10 + R20 * R20);
    float tx = R00 * rtn0, ty = R10 * rtn0, tz = R20 * rtn0;
    float2 u = cs2[0];
    float us = isL ? u.x : u.y;
    const bool lr = isL || isR;
    float Ffx = lr ? kN * ftanh(us * tx - pvx) : 0.0f;
    float Ffy = lr ? kN * ftanh(us * ty - pvy) : 0.0f;
    float Ffz = lr ? kN * ftanh(us * tz - pvz) : 0.0f;

    float* outb = out + (size_t)(half ? bB : bA) * T * 162;

    #pragma unroll 4
    for (int t = 0; t < T; ++t) {
        float rx = px - Xx, ry = py - Xy, rz = pz - Xz;

        float Ftx = Fsx + Ffx, Fty = Fsy + Ffy, Ftz = Fsz + Ffz;
        float tqx = ry * Ftz - rz * Fty;
        float tqy = rz * Ftx - rx * Ftz;
        float tqz = rx * Fty - ry * Ftx;

        /* fold I_inv and mass/mean scales into PER-LANE values (linearity):
           the post-reduction segment then starts at the integrator */
        float olx = tqx * I00 + tqy * I01 + tqz * I02;
        float oly = tqx * I10 + tqy * I11 + tqz * I12;
        float olz = tqx * I20 + tqy * I21 + tqz * I22;
        float alx = Ftx * AMUL, aly = Fty * AMUL, alz = Ftz * AMUL;

        /* next point state (old state only) */
        float npvx = Vx + (Wy * rz - Wz * ry);
        float npvy = Vy + (Wz * rx - Wx * rz);
        float npvz = Vz + (Wx * ry - Wy * rx);
        float npx = fmaf(npvx, RK4C, px);
        float npy = fmaf(npvy, RK4C, py);
        float npz = fmaf(npvz, RK4C, pz);

        int tn = (t + 1 < T) ? (t + 1) : t;
        float2 un = cs2[tn];

        /* spring stage for t+1 BEFORE the butterflies: its LDS/rsqrt
           latency rides under the 4-stage SHFL chain below */
        float nFsx, nFsy, nFsz, nkN;
        spring_calc(g, npx, npy, npz, npvx, npvy, npvz, nFsx, nFsy, nFsz, nkN);

        float odx = rsum16(olx), ody = rsum16(oly), odz = rsum16(olz);
        float ax  = rsum16(alx), ay  = rsum16(aly);
        float az  = rsum16(alz) - MGRAV * 0.025f;

        /* per-point stores in the SHFL shadow (old-step Fs/Ff) */
        float* o = outb + (size_t)t * 162;
        o[18  + 3 * p] = npx; o[19  + 3 * p] = npy; o[20  + 3 * p] = npz;
        o[66  + 3 * p] = Fsx; o[67  + 3 * p] = Fsy; o[68  + 3 * p] = Fsz;
        o[114 + 3 * p] = Ffx; o[115 + 3 * p] = Ffy; o[116 + 3 * p] = Ffz;

        float nVx = fmaf(ax, RK4C, Vx), nVy = fmaf(ay, RK4C, Vy), nVz = fmaf(az, RK4C, Vz);
        float nXx = fmaf(nVx, RK4C, Xx), nXy = fmaf(nVy, RK4C, Xy), nXz = fmaf(nVz, RK4C, Xz);
        float nWx = fmaf(odx, RK4C, Wx), nWy = fmaf(ody, RK4C, Wy), nWz = fmaf(odz, RK4C, Wz);

        /* Rodrigues, 3-term even polynomials in q = |w|^2 dt^2 */
        float ws = nWx * nWx + nWy * nWy + nWz * nWz;
        float q  = ws * DT2F;
        float sa = DTF * fmaf(q, fmaf(q, 1.0f/120.0f, -1.0f/6.0f), 1.0f);
        float ca = (0.5f * DT2F) * fmaf(q, fmaf(q, 1.0f/360.0f, -1.0f/12.0f), 1.0f);

        float Q01 = nWy * nWx, Q02 = nWz * nWx, Q12 = nWz * nWy;
        float Q00 = -(nWz * nWz + nWy * nWy);
        float Q11 = -(nWz * nWz + nWx * nWx);
        float Q22 = -(nWy * nWy + nWx * nWx);

        float A00 = 1.0f + Q00 * ca;
        float A01 = fmaf(-nWz, sa, Q01 * ca);
        float A02 = fmaf( nWy, sa, Q02 * ca);
        float A10 = fmaf( nWz, sa, Q01 * ca);
        float A11 = 1.0f + Q11 * ca;
        float A12 = fmaf(-nWx, sa, Q12 * ca);
        float A20 = fmaf(-nWy, sa, Q02 * ca);
        float A21 = fmaf( nWx, sa, Q12 * ca);
        float A22 = 1.0f + Q22 * ca;

        float nR00 = R00*A00 + R01*A10 + R02*A20;
        float nR01 = R00*A01 + R01*A11 + R02*A21;
        float nR02 = R00*A02 + R01*A12 + R02*A22;
        float nR10 = R10*A00 + R11*A10 + R12*A20;
        float nR11 = R10*A01 + R11*A11 + R12*A21;
        float nR12 = R10*A02 + R11*A12 + R12*A22;
        float nR20 = R20*A00 + R21*A10 + R22*A20;
        float nR21 = R20*A01 + R21*A11 + R22*A21;
        float nR22 = R20*A02 + R21*A12 + R22*A22;

        /* thrust via 1st-order rsqrt around 1 (R orthonormal to ~5e-5) */
        float ws2 = nR00 * nR00 + nR10 * nR10 + nR20 * nR20;
        float rtn = fmaf(-0.5f, ws2, 1.5f);
        tx = nR00 * rtn; ty = nR10 * rtn; tz = nR20 * rtn;

        /* friction for t+1 — issue tanh early, fill latency with stores */
        float usn = isL ? un.x : un.y;
        Ffx = lr ? nkN * ftanh(usn * tx - npvx) : 0.0f;
        Ffy = lr ? nkN * ftanh(usn * ty - npvy) : 0.0f;
        Ffz = lr ? nkN * ftanh(usn * tz - npvz) : 0.0f;

        /* body-state store in the tanh shadow: lane p stores value p */
        {
            float s0_0 = b0 ? nXy  : nXx;
            float s0_1 = b0 ? nVx  : nXz;
            float s0_2 = b0 ? nVz  : nVy;
            float s0_3 = b0 ? nWy  : nWx;
            float s0_4 = b0 ? nR00 : nWz;
            float s0_5 = b0 ? nR02 : nR01;
            float s0_6 = b0 ? nR11 : nR10;
            float s0_7 = b0 ? nR20 : nR12;
            float s1_0 = b1 ? s0_1 : s0_0;
            float s1_1 = b1 ? s0_3 : s0_2;
            float s1_2 = b1 ? s0_5 : s0_4;
            float s1_3 = b1 ? s0_7 : s0_6;
            float s2_0 = b2 ? s1_1 : s1_0;
            float s2_1 = b2 ? s1_3 : s1_2;
            float val  = b3 ? s2_1 : s2_0;
            o[p] = val;
            float ext = b0 ? nR22 : nR21;
            if (p < 2) o[16 + p] = ext;
        }

        /* commit */
        u = un;
        Fsx = nFsx; Fsy = nFsy; Fsz = nFsz; kN = nkN;
        Xx = nXx; Xy = nXy; Xz = nXz;
        Vx = nVx; Vy = nVy; Vz = nVz;
        Wx = nWx; Wy = nWy; Wz = nWz;
        px = npx; py = npy; pz = npz;
        pvx = npvx; pvy = npvy; pvz = npvz;
        R00 = nR00; R01 = nR01; R02 = nR02;
        R10 = nR10; R11 = nR11; R12 = nR12;
        R20 = nR20; R21 = nR21; R22 = nR22;
    }
}

extern "C" void kernel_launch(void* const* d_in, const int* in_sizes, int n_in,
                              void* d_out, int out_size)
{
    const float* z_grid   = (const float*)d_in[0];
    const float* controls = (const float*)d_in[1];
    const float* rpts     = (const float*)d_in[2];
    const float* Iinv     = (const float*)d_in[3];
    float*       out      = (float*)d_out;

    int B = in_sizes[0] / GRIDN;
    int T = in_sizes[1] / (B * 2);

    int nblk = (B + 1) / 2;
    size_t smem_bytes = (size_t)(2 * GRIDN + 4 * T) * sizeof(float);
    cudaFuncSetAttribute(physics_kernel,
                         cudaFuncAttributeMaxDynamicSharedMemorySize,
                         (int)smem_bytes);

    physics_kernel<<<nblk, 128, smem_bytes>>>(z_grid, controls, rpts, Iinv, out, B, T);
}